// round 4
// baseline (speedup 1.0000x reference)
#include <cuda_runtime.h>
#include <cuda_bf16.h>
#include <math.h>
#include <stdint.h>

// ---------------------------------------------------------------------------
// Problem constants
// ---------------------------------------------------------------------------
#define B_SZ 4
#define L_SZ 2048
#define G_SZ 2
#define D_SZ 2048
#define H_SZ 16
#define DE_SZ 64
#define E_SZ 1024          // GEMM K
#define N_SZ 32768
#define ROWS (B_SZ * L_SZ) // 8192
#define CD (G_SZ * D_SZ)   // 4096
#define NTOT 6144          // 4096 keyp + 2048 vproj
#define PAD 9
#define OUT_ELEMS ((size_t)ROWS * CD)
#define EPS_DEF 1.1920928955078125e-7f
#define EPS_SC 1e-5f
#define QSCALE 16256.0f    // 127*128

// GEMM tiling (int8): CTA 128x128, BK=64 int8 (2 k32 chunks), 3-stage cp.async
#define TILE_M 128
#define TILE_N 128
#define BK 64
#define NITER (E_SZ / BK)          // 16
#define STAGE_BYTES 32768          // Ah8K Al8K Bh8K Bl8K
#define NSTAGE 3
#define SMEM_TOTAL (NSTAGE * STAGE_BYTES) // 98304

// ---------------------------------------------------------------------------
// Scratch
// ---------------------------------------------------------------------------
__device__ int8_t g_qah[(size_t)ROWS * E_SZ];
__device__ int8_t g_qal[(size_t)ROWS * E_SZ];
__device__ int8_t g_qbh[(size_t)NTOT * E_SZ];
__device__ int8_t g_qbl[(size_t)NTOT * E_SZ];
__device__ float  g_sa[ROWS];
__device__ float  g_sb[NTOT];
__device__ float  g_keyp[(size_t)ROWS * CD];
__device__ float  g_vproj[(size_t)ROWS * D_SZ];
__device__ float  g_xn[(size_t)ROWS * CD];

// ---------------------------------------------------------------------------
// PTX helpers (family-agnostic)
// ---------------------------------------------------------------------------
__device__ __forceinline__ uint32_t smem_to_u32(const void* p) {
    uint32_t a;
    asm("{ .reg .u64 t; cvta.to.shared.u64 t, %1; cvt.u32.u64 %0, t; }"
        : "=r"(a) : "l"(p));
    return a;
}
__device__ __forceinline__ void cpasync16(uint32_t s, const void* g) {
    asm volatile("cp.async.cg.shared.global [%0], [%1], 16;" :: "r"(s), "l"(g));
}
#define CP_COMMIT() asm volatile("cp.async.commit_group;" ::: "memory")
#define CP_WAIT(n)  asm volatile("cp.async.wait_group %0;" :: "n"(n) : "memory")

__device__ __forceinline__ void ldsm4(uint32_t* r, uint32_t a) {
    asm volatile("ldmatrix.sync.aligned.m8n8.x4.shared.b16 {%0,%1,%2,%3}, [%4];"
        : "=r"(r[0]), "=r"(r[1]), "=r"(r[2]), "=r"(r[3]) : "r"(a));
}
__device__ __forceinline__ void imma16832(int* c, const uint32_t* a, const uint32_t* b) {
    asm volatile(
        "mma.sync.aligned.m16n8k32.row.col.s32.s8.s8.s32 "
        "{%0,%1,%2,%3}, {%4,%5,%6,%7}, {%8,%9}, {%0,%1,%2,%3};"
        : "+r"(c[0]), "+r"(c[1]), "+r"(c[2]), "+r"(c[3])
        : "r"(a[0]), "r"(a[1]), "r"(a[2]), "r"(a[3]), "r"(b[0]), "r"(b[1]));
}
__device__ __forceinline__ uint32_t sw32(uint32_t o) { return o ^ ((o >> 3) & 0x10); }

// ---------------------------------------------------------------------------
// Block-wide max of |x| (256 threads)
// ---------------------------------------------------------------------------
__device__ __forceinline__ float block_absmax(float m, float* red) {
    int lane = threadIdx.x & 31, w = threadIdx.x >> 5;
#pragma unroll
    for (int o = 16; o > 0; o >>= 1)
        m = fmaxf(m, __shfl_xor_sync(0xffffffffu, m, o));
    if (lane == 0) red[w] = m;
    __syncthreads();
    if (threadIdx.x == 0) {
        float a = red[0];
#pragma unroll
        for (int i = 1; i < 8; ++i) a = fmaxf(a, red[i]);
        red[0] = a;
    }
    __syncthreads();
    return red[0];
}

__device__ __forceinline__ void quant4(float4 v, float inv, char4* qh, char4* ql) {
    float q, ahf;
    char h[4], l[4];
    float vv[4] = {v.x, v.y, v.z, v.w};
#pragma unroll
    for (int j = 0; j < 4; ++j) {
        q = vv[j] * inv;
        ahf = rintf(q * (1.0f / 128.0f));
        h[j] = (char)(int)ahf;
        l[j] = (char)(int)rintf(q - 128.0f * ahf);
    }
    *qh = make_char4(h[0], h[1], h[2], h[3]);
    *ql = make_char4(l[0], l[1], l[2], l[3]);
}

// ---------------------------------------------------------------------------
// 1) Gather + quantize emb rows (block per row)
// ---------------------------------------------------------------------------
__global__ void __launch_bounds__(256) quant_emb(
    const int* __restrict__ ids, const float* __restrict__ table)
{
    __shared__ float red[8];
    int r = blockIdx.x, t = threadIdx.x;
    const int* idr = ids + r * H_SZ;
    int e  = t * 4;
    int h  = e >> 6;
    int de = e & 63;
    int id = idr[h];
    float4 v = *(const float4*)&table[((size_t)(h * N_SZ + id)) * DE_SZ + de];
    float m = fmaxf(fmaxf(fabsf(v.x), fabsf(v.y)), fmaxf(fabsf(v.z), fabsf(v.w)));
    float mx = block_absmax(m, red);
    float s = fmaxf(mx, 1e-30f) * (1.0f / QSCALE);
    if (t == 0) g_sa[r] = s;
    float inv = 1.0f / s;
    char4 qh, ql;
    quant4(v, inv, &qh, &ql);
    *(char4*)&g_qah[(size_t)r * E_SZ + e] = qh;
    *(char4*)&g_qal[(size_t)r * E_SZ + e] = ql;
}

// ---------------------------------------------------------------------------
// 2) Quantize weight rows: 0..4095 = Wk [G*D, E], 4096..6143 = Wv [D, E]
// ---------------------------------------------------------------------------
__global__ void __launch_bounds__(256) quant_w(
    const float* __restrict__ Wk, const float* __restrict__ Wv)
{
    __shared__ float red[8];
    int r = blockIdx.x, t = threadIdx.x;
    const float* src = (r < 4096) ? (Wk + (size_t)r * E_SZ)
                                  : (Wv + (size_t)(r - 4096) * E_SZ);
    float4 v = *(const float4*)&src[t * 4];
    float m = fmaxf(fmaxf(fabsf(v.x), fabsf(v.y)), fmaxf(fabsf(v.z), fabsf(v.w)));
    float mx = block_absmax(m, red);
    float s = fmaxf(mx, 1e-30f) * (1.0f / QSCALE);
    if (t == 0) g_sb[r] = s;
    float inv = 1.0f / s;
    char4 qh, ql;
    quant4(v, inv, &qh, &ql);
    *(char4*)&g_qbh[(size_t)r * E_SZ + t * 4] = qh;
    *(char4*)&g_qbl[(size_t)r * E_SZ + t * 4] = ql;
}

// ---------------------------------------------------------------------------
// 3) INT8 IMMA split GEMM: C[8192, 6144] = emb @ W^T (+bias), 3 terms
//    CTA 128x128, 8 warps (warp 64x32), BK=64, 3-stage cp.async.
//    Stage: Ah[2ch][128][32B] @0, Al @8K, Bh @16K, Bl @24K
// ---------------------------------------------------------------------------
__global__ void __launch_bounds__(256, 1) gemm_imma(
    const float* __restrict__ bk, const float* __restrict__ bv)
{
    extern __shared__ __align__(1024) char smem[];
    const uint32_t sbase = smem_to_u32(smem);
    const int tid = threadIdx.x;
    const int wid = tid >> 5;
    const int lane = tid & 31;
    const int m0 = blockIdx.y * TILE_M;
    const int n0 = blockIdx.x * TILE_N;

    const int wm = wid & 1;   // 64-row slab
    const int wn = wid >> 1;  // 32-col slab

    // fill: 2048 16B units per stage, 8 per thread
    auto fill = [&](int kt, int s) {
        const uint32_t st = sbase + (uint32_t)s * STAGE_BYTES;
        const int kb = kt * BK;
#pragma unroll
        for (int i = 0; i < 8; ++i) {
            int u = tid + i * 256;
            int isB = (u >= 1024);
            int v = u & 1023;
            int mat = v >> 9;           // 0=hi, 1=lo
            int w = v & 511;
            int r = w >> 2, q = w & 3;  // q: 16B unit within 64B row
            uint32_t a = st + isB * 16384 + mat * 8192 + (q >> 1) * 4096 +
                         sw32((uint32_t)(r * 32 + (q & 1) * 16));
            const int8_t* gp;
            if (!isB) gp = (mat ? g_qal : g_qah) + (size_t)(m0 + r) * E_SZ + kb + q * 16;
            else      gp = (mat ? g_qbl : g_qbh) + (size_t)(n0 + r) * E_SZ + kb + q * 16;
            cpasync16(a, gp);
        }
    };

    int acc1[4][4][4], acc2[4][4][4];
#pragma unroll
    for (int mi = 0; mi < 4; ++mi)
#pragma unroll
        for (int ni = 0; ni < 4; ++ni)
#pragma unroll
            for (int j = 0; j < 4; ++j) { acc1[mi][ni][j] = 0; acc2[mi][ni][j] = 0; }

    fill(0, 0); CP_COMMIT();
    fill(1, 1); CP_COMMIT();

    const uint32_t offA = sw32((uint32_t)((wm * 64 + (lane & 15)) * 32 + (lane >> 4) * 16));
    const uint32_t offB = sw32((uint32_t)((wn * 32 + ((lane >> 4) << 3) + (lane & 7)) * 32 +
                                          ((lane >> 3) & 1) * 16));

    for (int it = 0; it < NITER; ++it) {
        CP_WAIT(1);
        __syncthreads();
        if (it + 2 < NITER) { fill(it + 2, (it + 2) % NSTAGE); CP_COMMIT(); }

        const uint32_t st = sbase + (uint32_t)(it % NSTAGE) * STAGE_BYTES;
#pragma unroll
        for (int ch = 0; ch < 2; ++ch) {
            const uint32_t aH = st + ch * 4096 + offA;
            const uint32_t aL = st + 8192 + ch * 4096 + offA;
            const uint32_t bH = st + 16384 + ch * 4096 + offB;
            const uint32_t bL = st + 24576 + ch * 4096 + offB;

            uint32_t ah[4][4], al[4][4], bh[4][2], bl[4][2];
#pragma unroll
            for (int mi = 0; mi < 4; ++mi) {
                ldsm4(ah[mi], aH + (uint32_t)(mi * 16 * 32));
                ldsm4(al[mi], aL + (uint32_t)(mi * 16 * 32));
            }
#pragma unroll
            for (int np = 0; np < 2; ++np) {
                uint32_t r4[4];
                ldsm4(r4, bH + (uint32_t)(np * 16 * 32));
                bh[2 * np][0] = r4[0]; bh[2 * np][1] = r4[1];
                bh[2 * np + 1][0] = r4[2]; bh[2 * np + 1][1] = r4[3];
                ldsm4(r4, bL + (uint32_t)(np * 16 * 32));
                bl[2 * np][0] = r4[0]; bl[2 * np][1] = r4[1];
                bl[2 * np + 1][0] = r4[2]; bl[2 * np + 1][1] = r4[3];
            }
            // hh -> acc1
#pragma unroll
            for (int mi = 0; mi < 4; ++mi)
#pragma unroll
                for (int ni = 0; ni < 4; ++ni)
                    imma16832(acc1[mi][ni], ah[mi], bh[ni]);
            // hl + lh -> acc2
#pragma unroll
            for (int mi = 0; mi < 4; ++mi)
#pragma unroll
                for (int ni = 0; ni < 4; ++ni)
                    imma16832(acc2[mi][ni], ah[mi], bl[ni]);
#pragma unroll
            for (int mi = 0; mi < 4; ++mi)
#pragma unroll
                for (int ni = 0; ni < 4; ++ni)
                    imma16832(acc2[mi][ni], al[mi], bh[ni]);
        }
        __syncthreads();
    }

    // ---- epilogue: dequant + bias + store ----
    float* Cout; const float* bias; int ncols, c0;
    if (n0 < 4096) { Cout = g_keyp;  bias = bk; ncols = 4096; c0 = n0; }
    else           { Cout = g_vproj; bias = bv; ncols = 2048; c0 = n0 - 4096; }

    const int g = lane >> 2, tg = lane & 3;
#pragma unroll
    for (int mi = 0; mi < 4; ++mi) {
        int row0 = m0 + wm * 64 + mi * 16 + g;
        float sa0 = g_sa[row0], sa1 = g_sa[row0 + 8];
#pragma unroll
        for (int ni = 0; ni < 4; ++ni) {
            int ncol = n0 + wn * 32 + ni * 8 + tg * 2;
            int col  = c0 + wn * 32 + ni * 8 + tg * 2;
            float sb0 = g_sb[ncol], sb1 = g_sb[ncol + 1];
            float b0 = bias[col], b1 = bias[col + 1];
            float v00 = sa0 * sb0 * (16384.0f * (float)acc1[mi][ni][0] +
                                     128.0f * (float)acc2[mi][ni][0]) + b0;
            float v01 = sa0 * sb1 * (16384.0f * (float)acc1[mi][ni][1] +
                                     128.0f * (float)acc2[mi][ni][1]) + b1;
            float v10 = sa1 * sb0 * (16384.0f * (float)acc1[mi][ni][2] +
                                     128.0f * (float)acc2[mi][ni][2]) + b0;
            float v11 = sa1 * sb1 * (16384.0f * (float)acc1[mi][ni][3] +
                                     128.0f * (float)acc2[mi][ni][3]) + b1;
            float2 o0; o0.x = v00; o0.y = v01;
            float2 o1; o1.x = v10; o1.y = v11;
            *(float2*)&Cout[(size_t)row0 * ncols + col]       = o0;
            *(float2*)&Cout[(size_t)(row0 + 8) * ncols + col] = o1;
        }
    }
}

// ---------------------------------------------------------------------------
// 4) Fused gate/value/x_norm/cache
// ---------------------------------------------------------------------------
__global__ void __launch_bounds__(512) fuse_gate(
    const float* __restrict__ hid,
    const float* __restrict__ n1w, const float* __restrict__ n2w,
    const float* __restrict__ scw, float* __restrict__ out)
{
    int r = blockIdx.x;
    int t = threadIdx.x;
    const float* kp = g_keyp  + (size_t)r * CD;
    const float* hd = hid     + (size_t)r * CD;
    const float* vp = g_vproj + (size_t)r * D_SZ;

    float ssk0 = 0.f, ssk1 = 0.f, ssq0 = 0.f, ssq1 = 0.f;
    float cr0 = 0.f, cr1 = 0.f, sv = 0.f;
    float vrow[4];
#pragma unroll
    for (int i = 0; i < 4; ++i) {
        int d = t + i * 512;
        float kv0 = kp[d],        hv0 = hd[d];
        float kv1 = kp[2048 + d], hv1 = hd[2048 + d];
        ssk0 += kv0 * kv0; ssq0 += hv0 * hv0;
        cr0  += kv0 * hv0 * n1w[d] * n2w[d];
        ssk1 += kv1 * kv1; ssq1 += hv1 * hv1;
        cr1  += kv1 * hv1 * n1w[2048 + d] * n2w[2048 + d];
        float vv = vp[d];
        vrow[i] = vv;
        sv += vv * vv;
    }

    __shared__ float red[16][8];
    __shared__ float fin[4];
    float vals[7] = {ssk0, ssk1, ssq0, ssq1, cr0, cr1, sv};
    int lane = t & 31, w = t >> 5;
#pragma unroll
    for (int i = 0; i < 7; ++i) {
        float v = vals[i];
#pragma unroll
        for (int o = 16; o > 0; o >>= 1)
            v += __shfl_down_sync(0xffffffffu, v, o);
        if (lane == 0) red[w][i] = v;
    }
    __syncthreads();
    if (t == 0) {
        float s[7];
#pragma unroll
        for (int i = 0; i < 7; ++i) {
            float a = 0.f;
            for (int ww = 0; ww < 16; ++ww) a += red[ww][i];
            s[i] = a;
        }
        const float invD = 1.0f / 2048.0f;
        const float invSqrtD = 0.022097086912079610f;
#pragma unroll
        for (int gg = 0; gg < 2; ++gg) {
            float rsk = rsqrtf(s[gg] * invD + EPS_DEF);
            float rsq = rsqrtf(s[2 + gg] * invD + EPS_DEF);
            float gt  = rsk * rsq * s[4 + gg] * invSqrtD;
            float sg  = (gt > 0.f) ? 1.f : ((gt < 0.f) ? -1.f : 0.f);
            float sq  = sqrtf(fmaxf(fabsf(gt), 1e-6f)) * sg;
            float gate = 1.f / (1.f + expf(-sq));
            fin[gg]     = gate;
            fin[2 + gg] = rsqrtf(gate * gate * s[6] * invD + EPS_SC);
        }
    }
    __syncthreads();
    float g0 = fin[0], g1 = fin[1], inv0 = fin[2], inv1 = fin[3];

    int l = r & (L_SZ - 1);
    int b = r >> 11;
#pragma unroll
    for (int i = 0; i < 4; ++i) {
        int d = t + i * 512;
        float vv = vrow[i];
        float val0 = g0 * vv, val1 = g1 * vv;
        size_t base = (size_t)r * CD;
        out[base + d]        = val0;
        out[base + 2048 + d] = val1;
        float xn0 = val0 * inv0 * scw[d];
        float xn1 = val1 * inv1 * scw[2048 + d];
        g_xn[base + d]        = xn0;
        g_xn[base + 2048 + d] = xn1;
        if (l >= L_SZ - PAD) {
            int j = l - (L_SZ - PAD);
            size_t cbase = OUT_ELEMS + (size_t)b * CD * PAD;
            out[cbase + (size_t)d * PAD + j]          = xn0;
            out[cbase + (size_t)(2048 + d) * PAD + j] = xn1;
        }
    }
}

// ---------------------------------------------------------------------------
// 5) Depthwise dilated causal conv + silu + add
// ---------------------------------------------------------------------------
__global__ void __launch_bounds__(256) conv_silu_add(
    const float* __restrict__ cw, float* __restrict__ out)
{
    int idx = blockIdx.x * blockDim.x + threadIdx.x;
    int c = idx & (CD - 1);
    int r = idx >> 12;
    int l = r & (L_SZ - 1);
    float4 w = *(const float4*)(cw + c * 4);
    const float* x = g_xn;
    float acc;
    if (l >= 9) {
        acc = w.x * x[idx - 9 * CD] + w.y * x[idx - 6 * CD] +
              w.z * x[idx - 3 * CD] + w.w * x[idx];
    } else {
        acc = w.w * x[idx];
        if (l >= 3) acc += w.z * x[idx - 3 * CD];
        if (l >= 6) acc += w.y * x[idx - 6 * CD];
    }
    float y = acc / (1.f + expf(-acc));
    out[idx] += y;
}

// ---------------------------------------------------------------------------
// launch
// ---------------------------------------------------------------------------
extern "C" void kernel_launch(void* const* d_in, const int* in_sizes, int n_in,
                              void* d_out, int out_size)
{
    const float* hid   = (const float*)d_in[0];
    const int*   ids   = (const int*)  d_in[1];
    const float* table = (const float*)d_in[2];
    const float* Wk    = (const float*)d_in[3];
    const float* bk    = (const float*)d_in[4];
    const float* Wv    = (const float*)d_in[5];
    const float* bv    = (const float*)d_in[6];
    const float* n1    = (const float*)d_in[7];
    const float* n2    = (const float*)d_in[8];
    const float* cw    = (const float*)d_in[9];
    const float* scw   = (const float*)d_in[10];
    float* out = (float*)d_out;

    cudaFuncSetAttribute(gemm_imma, cudaFuncAttributeMaxDynamicSharedMemorySize,
                         SMEM_TOTAL);

    quant_w<<<NTOT, 256>>>(Wk, Wv);
    quant_emb<<<ROWS, 256>>>(ids, table);
    gemm_imma<<<dim3(NTOT / TILE_N, ROWS / TILE_M), 256, SMEM_TOTAL>>>(bk, bv);
    fuse_gate<<<ROWS, 512>>>(hid, n1, n2, scw, out);
    conv_silu_add<<<(int)(OUT_ELEMS / 256), 256>>>(cw, out);
}

// round 5
// speedup vs baseline: 2.5624x; 2.5624x over previous
#include <cuda_runtime.h>
#include <cuda_fp16.h>
#include <math.h>
#include <stdint.h>

// ---------------------------------------------------------------------------
// Problem constants
// ---------------------------------------------------------------------------
#define B_SZ 4
#define L_SZ 2048
#define G_SZ 2
#define D_SZ 2048
#define H_SZ 16
#define DE_SZ 64
#define E_SZ 1024          // GEMM K
#define N_SZ 32768
#define ROWS (B_SZ * L_SZ) // 8192
#define CD (G_SZ * D_SZ)   // 4096
#define NTOT 6144          // 4096 keyp + 2048 vproj
#define PAD 9
#define OUT_ELEMS ((size_t)ROWS * CD)
#define EPS_DEF 1.1920928955078125e-7f
#define EPS_SC 1e-5f

// GEMM tiling: CTA 128x256, BK=32, 8 warps (warp 64x64), 3-stage cp.async
#define TILE_M 128
#define TILE_N 256
#define BK 32
#define NITER (E_SZ / BK)          // 32
#define STAGE_BYTES 40960          // A 8K | Wh 16K | Wl 16K
#define NSTAGE 3
#define SMEM_TOTAL (NSTAGE * STAGE_BYTES) // 122880

// ---------------------------------------------------------------------------
// Scratch
// ---------------------------------------------------------------------------
__device__ __half g_ea[(size_t)ROWS * E_SZ];   // emb, fp16
__device__ __half g_wh[(size_t)NTOT * E_SZ];   // W hi
__device__ __half g_wl[(size_t)NTOT * E_SZ];   // W lo (subnormal-range fp16)
__device__ float  g_keyp[(size_t)ROWS * CD];
__device__ float  g_vproj[(size_t)ROWS * D_SZ];
__device__ float  g_xn[(size_t)ROWS * CD];

// ---------------------------------------------------------------------------
// PTX helpers (family-agnostic: cp.async / ldmatrix / mma.sync)
// ---------------------------------------------------------------------------
__device__ __forceinline__ uint32_t smem_to_u32(const void* p) {
    uint32_t a;
    asm("{ .reg .u64 t; cvta.to.shared.u64 t, %1; cvt.u32.u64 %0, t; }"
        : "=r"(a) : "l"(p));
    return a;
}
__device__ __forceinline__ void cpasync16(uint32_t s, const void* g) {
    asm volatile("cp.async.cg.shared.global [%0], [%1], 16;" :: "r"(s), "l"(g));
}
#define CP_COMMIT() asm volatile("cp.async.commit_group;" ::: "memory")
#define CP_WAIT(n)  asm volatile("cp.async.wait_group %0;" :: "n"(n) : "memory")

__device__ __forceinline__ void ldsm4(uint32_t* r, uint32_t a) {
    asm volatile("ldmatrix.sync.aligned.m8n8.x4.shared.b16 {%0,%1,%2,%3}, [%4];"
        : "=r"(r[0]), "=r"(r[1]), "=r"(r[2]), "=r"(r[3]) : "r"(a));
}
__device__ __forceinline__ void mma16816(float* c, const uint32_t* a, const uint32_t* b) {
    asm volatile(
        "mma.sync.aligned.m16n8k16.row.col.f32.f16.f16.f32 "
        "{%0,%1,%2,%3}, {%4,%5,%6,%7}, {%8,%9}, {%0,%1,%2,%3};"
        : "+f"(c[0]), "+f"(c[1]), "+f"(c[2]), "+f"(c[3])
        : "r"(a[0]), "r"(a[1]), "r"(a[2]), "r"(a[3]), "r"(b[0]), "r"(b[1]));
}
__device__ __forceinline__ uint32_t sw32(uint32_t o) { return o ^ ((o >> 3) & 0x10); }

// ---------------------------------------------------------------------------
// 1) Gather emb -> fp16
// ---------------------------------------------------------------------------
__global__ void __launch_bounds__(256) gather_h(
    const int* __restrict__ ids, const float* __restrict__ table)
{
    int r = blockIdx.x, t = threadIdx.x;
    const int* idr = ids + r * H_SZ;
    int e  = t * 4;
    int h  = e >> 6;
    int de = e & 63;
    int id = idr[h];
    float4 v = *(const float4*)&table[((size_t)(h * N_SZ + id)) * DE_SZ + de];
    __half2 p0, p1;
    p0.x = __float2half_rn(v.x); p0.y = __float2half_rn(v.y);
    p1.x = __float2half_rn(v.z); p1.y = __float2half_rn(v.w);
    *(__half2*)&g_ea[(size_t)r * E_SZ + e]     = p0;
    *(__half2*)&g_ea[(size_t)r * E_SZ + e + 2] = p1;
}

// ---------------------------------------------------------------------------
// 2) Weight split fp16 hi/lo: rows 0..4095 = Wk [G*D, E], 4096.. = Wv [D, E]
// ---------------------------------------------------------------------------
__global__ void __launch_bounds__(256) convert_w(
    const float* __restrict__ Wk, const float* __restrict__ Wv)
{
    size_t idx = ((size_t)blockIdx.x * 256 + threadIdx.x) * 4;
    size_t n = idx >> 10;
    const float* src = (n < 4096) ? (Wk + idx) : (Wv + (idx - (size_t)4096 * E_SZ));
    float4 v = *(const float4*)src;
    float vv[4] = {v.x, v.y, v.z, v.w};
    __half hi[4], lo[4];
#pragma unroll
    for (int j = 0; j < 4; ++j) {
        hi[j] = __float2half_rn(vv[j]);
        lo[j] = __float2half_rn(vv[j] - __half2float(hi[j]));
    }
    __half2 h0; h0.x = hi[0]; h0.y = hi[1];
    __half2 h1; h1.x = hi[2]; h1.y = hi[3];
    __half2 l0; l0.x = lo[0]; l0.y = lo[1];
    __half2 l1; l1.x = lo[2]; l1.y = lo[3];
    *(__half2*)&g_wh[idx]     = h0;
    *(__half2*)&g_wh[idx + 2] = h1;
    *(__half2*)&g_wl[idx]     = l0;
    *(__half2*)&g_wl[idx + 2] = l1;
}

// ---------------------------------------------------------------------------
// 3) fp16 2-term GEMM: C[8192, 6144] = emb @ (Wh+Wl)^T (+bias)
//    Stage: A[2ch][128][32B] @0, Wh[2ch][256][32B] @8K, Wl @24.5K
// ---------------------------------------------------------------------------
__global__ void __launch_bounds__(256, 1) gemm_mma(
    const float* __restrict__ bk, const float* __restrict__ bv)
{
    extern __shared__ __align__(1024) char smem[];
    const uint32_t sbase = smem_to_u32(smem);
    const int tid = threadIdx.x;
    const int wid = tid >> 5;
    const int lane = tid & 31;
    const int m0 = blockIdx.y * TILE_M;
    const int n0 = blockIdx.x * TILE_N;

    const int wm = wid & 1;   // 64-row slab
    const int wn = wid >> 1;  // 64-col slab

    // fill: 2560 16B units per stage, 10 per thread
    auto fill = [&](int kt, int s) {
        const uint32_t st = sbase + (uint32_t)s * STAGE_BYTES;
        const int kb = kt * BK;
#pragma unroll
        for (int i = 0; i < 10; ++i) {
            int u = tid + i * 256;
            if (u < 512) {          // A
                int r = u >> 2, q = u & 3;
                uint32_t a = st + (q >> 1) * 4096 +
                             sw32((uint32_t)(r * 32 + (q & 1) * 16));
                cpasync16(a, g_ea + (size_t)(m0 + r) * E_SZ + kb + q * 8);
            } else if (u < 1536) {  // Wh
                int v = u - 512;
                int r = v >> 2, q = v & 3;
                uint32_t a = st + 8192 + (q >> 1) * 8192 +
                             sw32((uint32_t)(r * 32 + (q & 1) * 16));
                cpasync16(a, g_wh + (size_t)(n0 + r) * E_SZ + kb + q * 8);
            } else {                // Wl
                int v = u - 1536;
                int r = v >> 2, q = v & 3;
                uint32_t a = st + 24576 + (q >> 1) * 8192 +
                             sw32((uint32_t)(r * 32 + (q & 1) * 16));
                cpasync16(a, g_wl + (size_t)(n0 + r) * E_SZ + kb + q * 8);
            }
        }
    };

    float acc[4][8][4];
#pragma unroll
    for (int mi = 0; mi < 4; ++mi)
#pragma unroll
        for (int ni = 0; ni < 8; ++ni)
#pragma unroll
            for (int j = 0; j < 4; ++j) acc[mi][ni][j] = 0.f;

    fill(0, 0); CP_COMMIT();
    fill(1, 1); CP_COMMIT();

    const uint32_t offA = sw32((uint32_t)((wm * 64 + (lane & 15)) * 32 + (lane >> 4) * 16));
    const uint32_t offB = sw32((uint32_t)((wn * 64 + ((lane >> 4) << 3) + (lane & 7)) * 32 +
                                          ((lane >> 3) & 1) * 16));

    for (int it = 0; it < NITER; ++it) {
        CP_WAIT(1);
        __syncthreads();
        if (it + 2 < NITER) { fill(it + 2, (it + 2) % NSTAGE); CP_COMMIT(); }

        const uint32_t st = sbase + (uint32_t)(it % NSTAGE) * STAGE_BYTES;
#pragma unroll
        for (int ch = 0; ch < 2; ++ch) {
            const uint32_t aA = st + ch * 4096 + offA;
            const uint32_t bH = st + 8192 + ch * 8192 + offB;
            const uint32_t bL = st + 24576 + ch * 8192 + offB;

            uint32_t av[4][4], bh[8][2], bl[8][2];
#pragma unroll
            for (int mi = 0; mi < 4; ++mi)
                ldsm4(av[mi], aA + (uint32_t)(mi * 16 * 32));
#pragma unroll
            for (int np = 0; np < 4; ++np) {
                uint32_t r4[4];
                ldsm4(r4, bH + (uint32_t)(np * 16 * 32));
                bh[2 * np][0] = r4[0]; bh[2 * np][1] = r4[1];
                bh[2 * np + 1][0] = r4[2]; bh[2 * np + 1][1] = r4[3];
                ldsm4(r4, bL + (uint32_t)(np * 16 * 32));
                bl[2 * np][0] = r4[0]; bl[2 * np][1] = r4[1];
                bl[2 * np + 1][0] = r4[2]; bl[2 * np + 1][1] = r4[3];
            }
            // term 1: A*Wh
#pragma unroll
            for (int mi = 0; mi < 4; ++mi)
#pragma unroll
                for (int ni = 0; ni < 8; ++ni)
                    mma16816(acc[mi][ni], av[mi], bh[ni]);
            // term 2: A*Wl (same accumulator)
#pragma unroll
            for (int mi = 0; mi < 4; ++mi)
#pragma unroll
                for (int ni = 0; ni < 8; ++ni)
                    mma16816(acc[mi][ni], av[mi], bl[ni]);
        }
        __syncthreads();
    }

    // ---- epilogue: bias + store ----
    float* Cout; const float* bias; int ncols, c0;
    if (n0 < 4096) { Cout = g_keyp;  bias = bk; ncols = 4096; c0 = n0; }
    else           { Cout = g_vproj; bias = bv; ncols = 2048; c0 = n0 - 4096; }

    const int g = lane >> 2, tg = lane & 3;
#pragma unroll
    for (int mi = 0; mi < 4; ++mi) {
        int row0 = m0 + wm * 64 + mi * 16 + g;
#pragma unroll
        for (int ni = 0; ni < 8; ++ni) {
            int col = c0 + wn * 64 + ni * 8 + tg * 2;
            float b0 = bias[col], b1 = bias[col + 1];
            float2 o0, o1;
            o0.x = acc[mi][ni][0] + b0; o0.y = acc[mi][ni][1] + b1;
            o1.x = acc[mi][ni][2] + b0; o1.y = acc[mi][ni][3] + b1;
            *(float2*)&Cout[(size_t)row0 * ncols + col]       = o0;
            *(float2*)&Cout[(size_t)(row0 + 8) * ncols + col] = o1;
        }
    }
}

// ---------------------------------------------------------------------------
// 4) Fused gate/value/x_norm/cache
// ---------------------------------------------------------------------------
__global__ void __launch_bounds__(512) fuse_gate(
    const float* __restrict__ hid,
    const float* __restrict__ n1w, const float* __restrict__ n2w,
    const float* __restrict__ scw, float* __restrict__ out)
{
    int r = blockIdx.x;
    int t = threadIdx.x;
    const float* kp = g_keyp  + (size_t)r * CD;
    const float* hd = hid     + (size_t)r * CD;
    const float* vp = g_vproj + (size_t)r * D_SZ;

    float ssk0 = 0.f, ssk1 = 0.f, ssq0 = 0.f, ssq1 = 0.f;
    float cr0 = 0.f, cr1 = 0.f, sv = 0.f;
    float vrow[4];
#pragma unroll
    for (int i = 0; i < 4; ++i) {
        int d = t + i * 512;
        float kv0 = kp[d],        hv0 = hd[d];
        float kv1 = kp[2048 + d], hv1 = hd[2048 + d];
        ssk0 += kv0 * kv0; ssq0 += hv0 * hv0;
        cr0  += kv0 * hv0 * n1w[d] * n2w[d];
        ssk1 += kv1 * kv1; ssq1 += hv1 * hv1;
        cr1  += kv1 * hv1 * n1w[2048 + d] * n2w[2048 + d];
        float vv = vp[d];
        vrow[i] = vv;
        sv += vv * vv;
    }

    __shared__ float red[16][8];
    __shared__ float fin[4];
    float vals[7] = {ssk0, ssk1, ssq0, ssq1, cr0, cr1, sv};
    int lane = t & 31, w = t >> 5;
#pragma unroll
    for (int i = 0; i < 7; ++i) {
        float v = vals[i];
#pragma unroll
        for (int o = 16; o > 0; o >>= 1)
            v += __shfl_down_sync(0xffffffffu, v, o);
        if (lane == 0) red[w][i] = v;
    }
    __syncthreads();
    if (t == 0) {
        float s[7];
#pragma unroll
        for (int i = 0; i < 7; ++i) {
            float a = 0.f;
            for (int ww = 0; ww < 16; ++ww) a += red[ww][i];
            s[i] = a;
        }
        const float invD = 1.0f / 2048.0f;
        const float invSqrtD = 0.022097086912079610f;
#pragma unroll
        for (int gg = 0; gg < 2; ++gg) {
            float rsk = rsqrtf(s[gg] * invD + EPS_DEF);
            float rsq = rsqrtf(s[2 + gg] * invD + EPS_DEF);
            float gt  = rsk * rsq * s[4 + gg] * invSqrtD;
            float sg  = (gt > 0.f) ? 1.f : ((gt < 0.f) ? -1.f : 0.f);
            float sq  = sqrtf(fmaxf(fabsf(gt), 1e-6f)) * sg;
            float gate = 1.f / (1.f + expf(-sq));
            fin[gg]     = gate;
            fin[2 + gg] = rsqrtf(gate * gate * s[6] * invD + EPS_SC);
        }
    }
    __syncthreads();
    float g0 = fin[0], g1 = fin[1], inv0 = fin[2], inv1 = fin[3];

    int l = r & (L_SZ - 1);
    int b = r >> 11;
#pragma unroll
    for (int i = 0; i < 4; ++i) {
        int d = t + i * 512;
        float vv = vrow[i];
        float val0 = g0 * vv, val1 = g1 * vv;
        size_t base = (size_t)r * CD;
        out[base + d]        = val0;
        out[base + 2048 + d] = val1;
        float xn0 = val0 * inv0 * scw[d];
        float xn1 = val1 * inv1 * scw[2048 + d];
        g_xn[base + d]        = xn0;
        g_xn[base + 2048 + d] = xn1;
        if (l >= L_SZ - PAD) {
            int j = l - (L_SZ - PAD);
            size_t cbase = OUT_ELEMS + (size_t)b * CD * PAD;
            out[cbase + (size_t)d * PAD + j]          = xn0;
            out[cbase + (size_t)(2048 + d) * PAD + j] = xn1;
        }
    }
}

// ---------------------------------------------------------------------------
// 5) Depthwise dilated causal conv + silu + add
// ---------------------------------------------------------------------------
__global__ void __launch_bounds__(256) conv_silu_add(
    const float* __restrict__ cw, float* __restrict__ out)
{
    int idx = blockIdx.x * blockDim.x + threadIdx.x;
    int c = idx & (CD - 1);
    int r = idx >> 12;
    int l = r & (L_SZ - 1);
    float4 w = *(const float4*)(cw + c * 4);
    const float* x = g_xn;
    float acc;
    if (l >= 9) {
        acc = w.x * x[idx - 9 * CD] + w.y * x[idx - 6 * CD] +
              w.z * x[idx - 3 * CD] + w.w * x[idx];
    } else {
        acc = w.w * x[idx];
        if (l >= 3) acc += w.z * x[idx - 3 * CD];
        if (l >= 6) acc += w.y * x[idx - 6 * CD];
    }
    float y = acc / (1.f + expf(-acc));
    out[idx] += y;
}

// ---------------------------------------------------------------------------
// launch
// ---------------------------------------------------------------------------
extern "C" void kernel_launch(void* const* d_in, const int* in_sizes, int n_in,
                              void* d_out, int out_size)
{
    const float* hid   = (const float*)d_in[0];
    const int*   ids   = (const int*)  d_in[1];
    const float* table = (const float*)d_in[2];
    const float* Wk    = (const float*)d_in[3];
    const float* bk    = (const float*)d_in[4];
    const float* Wv    = (const float*)d_in[5];
    const float* bv    = (const float*)d_in[6];
    const float* n1    = (const float*)d_in[7];
    const float* n2    = (const float*)d_in[8];
    const float* cw    = (const float*)d_in[9];
    const float* scw   = (const float*)d_in[10];
    float* out = (float*)d_out;

    cudaFuncSetAttribute(gemm_mma, cudaFuncAttributeMaxDynamicSharedMemorySize,
                         SMEM_TOTAL);

    convert_w<<<(NTOT * E_SZ / 4) / 256, 256>>>(Wk, Wv);
    gather_h<<<ROWS, 256>>>(ids, table);
    gemm_mma<<<dim3(NTOT / TILE_N, ROWS / TILE_M), 256, SMEM_TOTAL>>>(bk, bv);
    fuse_gate<<<ROWS, 512>>>(hid, n1, n2, scw, out);
    conv_silu_add<<<(int)(OUT_ELEMS / 256), 256>>>(cw, out);
}

// round 6
// speedup vs baseline: 3.6922x; 1.4409x over previous
#include <cuda_runtime.h>
#include <cuda_fp16.h>
#include <math.h>
#include <stdint.h>

// ---------------------------------------------------------------------------
// Problem constants
// ---------------------------------------------------------------------------
#define B_SZ 4
#define L_SZ 2048
#define G_SZ 2
#define D_SZ 2048
#define H_SZ 16
#define DE_SZ 64
#define E_SZ 1024          // GEMM K
#define N_SZ 32768
#define ROWS (B_SZ * L_SZ) // 8192
#define CD (G_SZ * D_SZ)   // 4096
#define NTOT 6144          // 4096 keyp + 2048 vproj
#define PAD 9
#define OUT_ELEMS ((size_t)ROWS * CD)
#define EPS_DEF 1.1920928955078125e-7f
#define EPS_SC 1e-5f

// GEMM tiling: CTA 128x256, BK=32, 8 warps (warp 64x64), 3-stage cp.async
#define TILE_M 128
#define TILE_N 256
#define BK 32
#define NITER (E_SZ / BK)          // 32
#define STAGE_BYTES 24576          // A 8K | W 16K
#define NSTAGE 3
#define SMEM_TOTAL (NSTAGE * STAGE_BYTES) // 73728

// ---------------------------------------------------------------------------
// Scratch
// ---------------------------------------------------------------------------
__device__ __half g_ea[(size_t)ROWS * E_SZ];   // emb, fp16
__device__ __half g_wh[(size_t)NTOT * E_SZ];   // W, fp16
__device__ float  g_keyp[(size_t)ROWS * CD];
__device__ float  g_vproj[(size_t)ROWS * D_SZ];
__device__ float  g_xn[(size_t)ROWS * CD];

// ---------------------------------------------------------------------------
// PTX helpers (family-agnostic: cp.async / ldmatrix / mma.sync)
// ---------------------------------------------------------------------------
__device__ __forceinline__ uint32_t smem_to_u32(const void* p) {
    uint32_t a;
    asm("{ .reg .u64 t; cvta.to.shared.u64 t, %1; cvt.u32.u64 %0, t; }"
        : "=r"(a) : "l"(p));
    return a;
}
__device__ __forceinline__ void cpasync16(uint32_t s, const void* g) {
    asm volatile("cp.async.cg.shared.global [%0], [%1], 16;" :: "r"(s), "l"(g));
}
#define CP_COMMIT() asm volatile("cp.async.commit_group;" ::: "memory")
#define CP_WAIT(n)  asm volatile("cp.async.wait_group %0;" :: "n"(n) : "memory")

__device__ __forceinline__ void ldsm4(uint32_t* r, uint32_t a) {
    asm volatile("ldmatrix.sync.aligned.m8n8.x4.shared.b16 {%0,%1,%2,%3}, [%4];"
        : "=r"(r[0]), "=r"(r[1]), "=r"(r[2]), "=r"(r[3]) : "r"(a));
}
__device__ __forceinline__ void mma16816(float* c, const uint32_t* a, const uint32_t* b) {
    asm volatile(
        "mma.sync.aligned.m16n8k16.row.col.f32.f16.f16.f32 "
        "{%0,%1,%2,%3}, {%4,%5,%6,%7}, {%8,%9}, {%0,%1,%2,%3};"
        : "+f"(c[0]), "+f"(c[1]), "+f"(c[2]), "+f"(c[3])
        : "r"(a[0]), "r"(a[1]), "r"(a[2]), "r"(a[3]), "r"(b[0]), "r"(b[1]));
}
__device__ __forceinline__ uint32_t sw32(uint32_t o) { return o ^ ((o >> 3) & 0x10); }

// ---------------------------------------------------------------------------
// 1) Gather emb -> fp16
// ---------------------------------------------------------------------------
__global__ void __launch_bounds__(256) gather_h(
    const int* __restrict__ ids, const float* __restrict__ table)
{
    int r = blockIdx.x, t = threadIdx.x;
    const int* idr = ids + r * H_SZ;
    int e  = t * 4;
    int h  = e >> 6;
    int de = e & 63;
    int id = idr[h];
    float4 v = *(const float4*)&table[((size_t)(h * N_SZ + id)) * DE_SZ + de];
    __half2 p0, p1;
    p0.x = __float2half_rn(v.x); p0.y = __float2half_rn(v.y);
    p1.x = __float2half_rn(v.z); p1.y = __float2half_rn(v.w);
    *(__half2*)&g_ea[(size_t)r * E_SZ + e]     = p0;
    *(__half2*)&g_ea[(size_t)r * E_SZ + e + 2] = p1;
}

// ---------------------------------------------------------------------------
// 2) Weight -> fp16: rows 0..4095 = Wk [G*D, E], 4096.. = Wv [D, E]
// ---------------------------------------------------------------------------
__global__ void __launch_bounds__(256) convert_w(
    const float* __restrict__ Wk, const float* __restrict__ Wv)
{
    size_t idx = ((size_t)blockIdx.x * 256 + threadIdx.x) * 4;
    size_t n = idx >> 10;
    const float* src = (n < 4096) ? (Wk + idx) : (Wv + (idx - (size_t)4096 * E_SZ));
    float4 v = *(const float4*)src;
    __half2 h0, h1;
    h0.x = __float2half_rn(v.x); h0.y = __float2half_rn(v.y);
    h1.x = __float2half_rn(v.z); h1.y = __float2half_rn(v.w);
    *(__half2*)&g_wh[idx]     = h0;
    *(__half2*)&g_wh[idx + 2] = h1;
}

// ---------------------------------------------------------------------------
// 3) fp16 GEMM: C[8192, 6144] = emb @ W^T (+bias)
//    Stage: A[2ch][128][32B] @0, W[2ch][256][32B] @8K
// ---------------------------------------------------------------------------
__global__ void __launch_bounds__(256, 1) gemm_mma(
    const float* __restrict__ bk, const float* __restrict__ bv)
{
    extern __shared__ __align__(1024) char smem[];
    const uint32_t sbase = smem_to_u32(smem);
    const int tid = threadIdx.x;
    const int wid = tid >> 5;
    const int lane = tid & 31;
    const int m0 = blockIdx.y * TILE_M;
    const int n0 = blockIdx.x * TILE_N;

    const int wm = wid & 1;   // 64-row slab
    const int wn = wid >> 1;  // 64-col slab

    // fill: 1536 16B units per stage, 6 per thread
    auto fill = [&](int kt, int s) {
        const uint32_t st = sbase + (uint32_t)s * STAGE_BYTES;
        const int kb = kt * BK;
#pragma unroll
        for (int i = 0; i < 6; ++i) {
            int u = tid + i * 256;
            if (u < 512) {          // A
                int r = u >> 2, q = u & 3;
                uint32_t a = st + (q >> 1) * 4096 +
                             sw32((uint32_t)(r * 32 + (q & 1) * 16));
                cpasync16(a, g_ea + (size_t)(m0 + r) * E_SZ + kb + q * 8);
            } else {                // W
                int v = u - 512;
                int r = v >> 2, q = v & 3;
                uint32_t a = st + 8192 + (q >> 1) * 8192 +
                             sw32((uint32_t)(r * 32 + (q & 1) * 16));
                cpasync16(a, g_wh + (size_t)(n0 + r) * E_SZ + kb + q * 8);
            }
        }
    };

    float acc[4][8][4];
#pragma unroll
    for (int mi = 0; mi < 4; ++mi)
#pragma unroll
        for (int ni = 0; ni < 8; ++ni)
#pragma unroll
            for (int j = 0; j < 4; ++j) acc[mi][ni][j] = 0.f;

    fill(0, 0); CP_COMMIT();
    fill(1, 1); CP_COMMIT();

    const uint32_t offA = sw32((uint32_t)((wm * 64 + (lane & 15)) * 32 + (lane >> 4) * 16));
    const uint32_t offB = sw32((uint32_t)((wn * 64 + ((lane >> 4) << 3) + (lane & 7)) * 32 +
                                          ((lane >> 3) & 1) * 16));

    for (int it = 0; it < NITER; ++it) {
        CP_WAIT(1);
        __syncthreads();
        if (it + 2 < NITER) { fill(it + 2, (it + 2) % NSTAGE); CP_COMMIT(); }

        const uint32_t st = sbase + (uint32_t)(it % NSTAGE) * STAGE_BYTES;
#pragma unroll
        for (int ch = 0; ch < 2; ++ch) {
            const uint32_t aA = st + ch * 4096 + offA;
            const uint32_t bW = st + 8192 + ch * 8192 + offB;

            uint32_t av[4][4], bw[8][2];
#pragma unroll
            for (int mi = 0; mi < 4; ++mi)
                ldsm4(av[mi], aA + (uint32_t)(mi * 16 * 32));
#pragma unroll
            for (int np = 0; np < 4; ++np) {
                uint32_t r4[4];
                ldsm4(r4, bW + (uint32_t)(np * 16 * 32));
                bw[2 * np][0] = r4[0]; bw[2 * np][1] = r4[1];
                bw[2 * np + 1][0] = r4[2]; bw[2 * np + 1][1] = r4[3];
            }
#pragma unroll
            for (int mi = 0; mi < 4; ++mi)
#pragma unroll
                for (int ni = 0; ni < 8; ++ni)
                    mma16816(acc[mi][ni], av[mi], bw[ni]);
        }
        __syncthreads();
    }

    // ---- epilogue: bias + store ----
    float* Cout; const float* bias; int ncols, c0;
    if (n0 < 4096) { Cout = g_keyp;  bias = bk; ncols = 4096; c0 = n0; }
    else           { Cout = g_vproj; bias = bv; ncols = 2048; c0 = n0 - 4096; }

    const int g = lane >> 2, tg = lane & 3;
#pragma unroll
    for (int mi = 0; mi < 4; ++mi) {
        int row0 = m0 + wm * 64 + mi * 16 + g;
#pragma unroll
        for (int ni = 0; ni < 8; ++ni) {
            int col = c0 + wn * 64 + ni * 8 + tg * 2;
            float b0 = bias[col], b1 = bias[col + 1];
            float2 o0, o1;
            o0.x = acc[mi][ni][0] + b0; o0.y = acc[mi][ni][1] + b1;
            o1.x = acc[mi][ni][2] + b0; o1.y = acc[mi][ni][3] + b1;
            *(float2*)&Cout[(size_t)row0 * ncols + col]       = o0;
            *(float2*)&Cout[(size_t)(row0 + 8) * ncols + col] = o1;
        }
    }
}

// ---------------------------------------------------------------------------
// 4) Fused gate/value/x_norm/cache
// ---------------------------------------------------------------------------
__global__ void __launch_bounds__(512) fuse_gate(
    const float* __restrict__ hid,
    const float* __restrict__ n1w, const float* __restrict__ n2w,
    const float* __restrict__ scw, float* __restrict__ out)
{
    int r = blockIdx.x;
    int t = threadIdx.x;
    const float* kp = g_keyp  + (size_t)r * CD;
    const float* hd = hid     + (size_t)r * CD;
    const float* vp = g_vproj + (size_t)r * D_SZ;

    float ssk0 = 0.f, ssk1 = 0.f, ssq0 = 0.f, ssq1 = 0.f;
    float cr0 = 0.f, cr1 = 0.f, sv = 0.f;
    float vrow[4];
#pragma unroll
    for (int i = 0; i < 4; ++i) {
        int d = t + i * 512;
        float kv0 = kp[d],        hv0 = hd[d];
        float kv1 = kp[2048 + d], hv1 = hd[2048 + d];
        ssk0 += kv0 * kv0; ssq0 += hv0 * hv0;
        cr0  += kv0 * hv0 * n1w[d] * n2w[d];
        ssk1 += kv1 * kv1; ssq1 += hv1 * hv1;
        cr1  += kv1 * hv1 * n1w[2048 + d] * n2w[2048 + d];
        float vv = vp[d];
        vrow[i] = vv;
        sv += vv * vv;
    }

    __shared__ float red[16][8];
    __shared__ float fin[4];
    float vals[7] = {ssk0, ssk1, ssq0, ssq1, cr0, cr1, sv};
    int lane = t & 31, w = t >> 5;
#pragma unroll
    for (int i = 0; i < 7; ++i) {
        float v = vals[i];
#pragma unroll
        for (int o = 16; o > 0; o >>= 1)
            v += __shfl_down_sync(0xffffffffu, v, o);
        if (lane == 0) red[w][i] = v;
    }
    __syncthreads();
    if (t == 0) {
        float s[7];
#pragma unroll
        for (int i = 0; i < 7; ++i) {
            float a = 0.f;
            for (int ww = 0; ww < 16; ++ww) a += red[ww][i];
            s[i] = a;
        }
        const float invD = 1.0f / 2048.0f;
        const float invSqrtD = 0.022097086912079610f;
#pragma unroll
        for (int gg = 0; gg < 2; ++gg) {
            float rsk = rsqrtf(s[gg] * invD + EPS_DEF);
            float rsq = rsqrtf(s[2 + gg] * invD + EPS_DEF);
            float gt  = rsk * rsq * s[4 + gg] * invSqrtD;
            float sg  = (gt > 0.f) ? 1.f : ((gt < 0.f) ? -1.f : 0.f);
            float sq  = sqrtf(fmaxf(fabsf(gt), 1e-6f)) * sg;
            float gate = 1.f / (1.f + expf(-sq));
            fin[gg]     = gate;
            fin[2 + gg] = rsqrtf(gate * gate * s[6] * invD + EPS_SC);
        }
    }
    __syncthreads();
    float g0 = fin[0], g1 = fin[1], inv0 = fin[2], inv1 = fin[3];

    int l = r & (L_SZ - 1);
    int b = r >> 11;
#pragma unroll
    for (int i = 0; i < 4; ++i) {
        int d = t + i * 512;
        float vv = vrow[i];
        float val0 = g0 * vv, val1 = g1 * vv;
        size_t base = (size_t)r * CD;
        out[base + d]        = val0;
        out[base + 2048 + d] = val1;
        float xn0 = val0 * inv0 * scw[d];
        float xn1 = val1 * inv1 * scw[2048 + d];
        g_xn[base + d]        = xn0;
        g_xn[base + 2048 + d] = xn1;
        if (l >= L_SZ - PAD) {
            int j = l - (L_SZ - PAD);
            size_t cbase = OUT_ELEMS + (size_t)b * CD * PAD;
            out[cbase + (size_t)d * PAD + j]          = xn0;
            out[cbase + (size_t)(2048 + d) * PAD + j] = xn1;
        }
    }
}

// ---------------------------------------------------------------------------
// 5) Depthwise dilated causal conv + silu + add
// ---------------------------------------------------------------------------
__global__ void __launch_bounds__(256) conv_silu_add(
    const float* __restrict__ cw, float* __restrict__ out)
{
    int idx = blockIdx.x * blockDim.x + threadIdx.x;
    int c = idx & (CD - 1);
    int r = idx >> 12;
    int l = r & (L_SZ - 1);
    float4 w = *(const float4*)(cw + c * 4);
    const float* x = g_xn;
    float acc;
    if (l >= 9) {
        acc = w.x * x[idx - 9 * CD] + w.y * x[idx - 6 * CD] +
              w.z * x[idx - 3 * CD] + w.w * x[idx];
    } else {
        acc = w.w * x[idx];
        if (l >= 3) acc += w.z * x[idx - 3 * CD];
        if (l >= 6) acc += w.y * x[idx - 6 * CD];
    }
    float y = acc / (1.f + expf(-acc));
    out[idx] += y;
}

// ---------------------------------------------------------------------------
// launch
// ---------------------------------------------------------------------------
extern "C" void kernel_launch(void* const* d_in, const int* in_sizes, int n_in,
                              void* d_out, int out_size)
{
    const float* hid   = (const float*)d_in[0];
    const int*   ids   = (const int*)  d_in[1];
    const float* table = (const float*)d_in[2];
    const float* Wk    = (const float*)d_in[3];
    const float* bk    = (const float*)d_in[4];
    const float* Wv    = (const float*)d_in[5];
    const float* bv    = (const float*)d_in[6];
    const float* n1    = (const float*)d_in[7];
    const float* n2    = (const float*)d_in[8];
    const float* cw    = (const float*)d_in[9];
    const float* scw   = (const float*)d_in[10];
    float* out = (float*)d_out;

    cudaFuncSetAttribute(gemm_mma, cudaFuncAttributeMaxDynamicSharedMemorySize,
                         SMEM_TOTAL);

    convert_w<<<(NTOT * E_SZ / 4) / 256, 256>>>(Wk, Wv);
    gather_h<<<ROWS, 256>>>(ids, table);
    gemm_mma<<<dim3(NTOT / TILE_N, ROWS / TILE_M), 256, SMEM_TOTAL>>>(bk, bv);
    fuse_gate<<<ROWS, 512>>>(hid, n1, n2, scw, out);
    conv_silu_add<<<(int)(OUT_ELEMS / 256), 256>>>(cw, out);
}

// round 7
// speedup vs baseline: 4.2998x; 1.1646x over previous
#include <cuda_runtime.h>
#include <cuda_fp16.h>
#include <math.h>
#include <stdint.h>

// ---------------------------------------------------------------------------
// Problem constants
// ---------------------------------------------------------------------------
#define B_SZ 4
#define L_SZ 2048
#define G_SZ 2
#define D_SZ 2048
#define H_SZ 16
#define DE_SZ 64
#define E_SZ 1024
#define N_SZ 32768
#define ROWS (B_SZ * L_SZ)  // 8192
#define CD (G_SZ * D_SZ)    // 4096
#define NTOT 6144
#define PAD 9
#define OUT_ELEMS ((size_t)ROWS * CD)
#define EPS_DEF 1.1920928955078125e-7f
#define EPS_SC 1e-5f

#define TILE_M 128
#define TILE_N 256
#define BK 32
#define NITER (E_SZ / BK)
#define STAGE_BYTES 24576
#define NSTAGE 3
#define SMEM_TOTAL (NSTAGE * STAGE_BYTES)

// ---------------------------------------------------------------------------
// Scratch
// ---------------------------------------------------------------------------
__device__ __half g_ea[(size_t)ROWS * E_SZ];
__device__ __half g_wh[(size_t)NTOT * E_SZ];     // rows 0..4095 Wk, 4096.. Wv
__device__ float  g_vpb[(size_t)ROWS * D_SZ];    // vproj + bv
__device__ float  g_partK[(size_t)ROWS * 16 * 3]; // per-row/ctacol {ssk, cr, ssq}
__device__ float  g_partV[(size_t)ROWS * 8];      // per-row/ctacol sv
__device__ float4 g_rs[ROWS];                     // {gate0, gate1, q0, q1}

// ---------------------------------------------------------------------------
// PTX helpers
// ---------------------------------------------------------------------------
__device__ __forceinline__ uint32_t smem_to_u32(const void* p) {
    uint32_t a;
    asm("{ .reg .u64 t; cvta.to.shared.u64 t, %1; cvt.u32.u64 %0, t; }"
        : "=r"(a) : "l"(p));
    return a;
}
__device__ __forceinline__ void cpasync16(uint32_t s, const void* g) {
    asm volatile("cp.async.cg.shared.global [%0], [%1], 16;" :: "r"(s), "l"(g));
}
#define CP_COMMIT() asm volatile("cp.async.commit_group;" ::: "memory")
#define CP_WAIT(n)  asm volatile("cp.async.wait_group %0;" :: "n"(n) : "memory")

__device__ __forceinline__ void ldsm4(uint32_t* r, uint32_t a) {
    asm volatile("ldmatrix.sync.aligned.m8n8.x4.shared.b16 {%0,%1,%2,%3}, [%4];"
        : "=r"(r[0]), "=r"(r[1]), "=r"(r[2]), "=r"(r[3]) : "r"(a));
}
__device__ __forceinline__ void mma16816(float* c, const uint32_t* a, const uint32_t* b) {
    asm volatile(
        "mma.sync.aligned.m16n8k16.row.col.f32.f16.f16.f32 "
        "{%0,%1,%2,%3}, {%4,%5,%6,%7}, {%8,%9}, {%0,%1,%2,%3};"
        : "+f"(c[0]), "+f"(c[1]), "+f"(c[2]), "+f"(c[3])
        : "r"(a[0]), "r"(a[1]), "r"(a[2]), "r"(a[3]), "r"(b[0]), "r"(b[1]));
}
__device__ __forceinline__ uint32_t sw32(uint32_t o) { return o ^ ((o >> 3) & 0x10); }

// ---------------------------------------------------------------------------
// 1) Gather emb -> fp16
// ---------------------------------------------------------------------------
__global__ void __launch_bounds__(256) gather_h(
    const int* __restrict__ ids, const float* __restrict__ table)
{
    int r = blockIdx.x, t = threadIdx.x;
    const int* idr = ids + r * H_SZ;
    int e  = t * 4;
    int h  = e >> 6;
    int de = e & 63;
    int id = idr[h];
    float4 v = *(const float4*)&table[((size_t)(h * N_SZ + id)) * DE_SZ + de];
    __half2 p0, p1;
    p0.x = __float2half_rn(v.x); p0.y = __float2half_rn(v.y);
    p1.x = __float2half_rn(v.z); p1.y = __float2half_rn(v.w);
    *(__half2*)&g_ea[(size_t)r * E_SZ + e]     = p0;
    *(__half2*)&g_ea[(size_t)r * E_SZ + e + 2] = p1;
}

// ---------------------------------------------------------------------------
// 2) Weight -> fp16
// ---------------------------------------------------------------------------
__global__ void __launch_bounds__(256) convert_w(
    const float* __restrict__ Wk, const float* __restrict__ Wv)
{
    size_t idx = ((size_t)blockIdx.x * 256 + threadIdx.x) * 4;
    size_t n = idx >> 10;
    const float* src = (n < 4096) ? (Wk + idx) : (Wv + (idx - (size_t)4096 * E_SZ));
    float4 v = *(const float4*)src;
    __half2 h0, h1;
    h0.x = __float2half_rn(v.x); h0.y = __float2half_rn(v.y);
    h1.x = __float2half_rn(v.z); h1.y = __float2half_rn(v.w);
    *(__half2*)&g_wh[idx]     = h0;
    *(__half2*)&g_wh[idx + 2] = h1;
}

// ---------------------------------------------------------------------------
// Shared fp16 GEMM mainloop: acc[4][8][4] = A[m0:+128] @ W[n0w:+256]^T
// ---------------------------------------------------------------------------
__device__ __forceinline__ void gemm_mainloop(
    char* smem, uint32_t sbase, int m0, int n0w,
    int tid, int wid, int lane, int wm, int wn, float acc[4][8][4])
{
    auto fill = [&](int kt, int s) {
        const uint32_t st = sbase + (uint32_t)s * STAGE_BYTES;
        const int kb = kt * BK;
#pragma unroll
        for (int i = 0; i < 6; ++i) {
            int u = tid + i * 256;
            if (u < 512) {
                int r = u >> 2, q = u & 3;
                uint32_t a = st + (q >> 1) * 4096 +
                             sw32((uint32_t)(r * 32 + (q & 1) * 16));
                cpasync16(a, g_ea + (size_t)(m0 + r) * E_SZ + kb + q * 8);
            } else {
                int v = u - 512;
                int r = v >> 2, q = v & 3;
                uint32_t a = st + 8192 + (q >> 1) * 8192 +
                             sw32((uint32_t)(r * 32 + (q & 1) * 16));
                cpasync16(a, g_wh + (size_t)(n0w + r) * E_SZ + kb + q * 8);
            }
        }
    };

#pragma unroll
    for (int mi = 0; mi < 4; ++mi)
#pragma unroll
        for (int ni = 0; ni < 8; ++ni)
#pragma unroll
            for (int j = 0; j < 4; ++j) acc[mi][ni][j] = 0.f;

    fill(0, 0); CP_COMMIT();
    fill(1, 1); CP_COMMIT();

    const uint32_t offA = sw32((uint32_t)((wm * 64 + (lane & 15)) * 32 + (lane >> 4) * 16));
    const uint32_t offB = sw32((uint32_t)((wn * 64 + ((lane >> 4) << 3) + (lane & 7)) * 32 +
                                          ((lane >> 3) & 1) * 16));

    for (int it = 0; it < NITER; ++it) {
        CP_WAIT(1);
        __syncthreads();
        if (it + 2 < NITER) { fill(it + 2, (it + 2) % NSTAGE); CP_COMMIT(); }

        const uint32_t st = sbase + (uint32_t)(it % NSTAGE) * STAGE_BYTES;
#pragma unroll
        for (int ch = 0; ch < 2; ++ch) {
            const uint32_t aA = st + ch * 4096 + offA;
            const uint32_t bW = st + 8192 + ch * 8192 + offB;
            uint32_t av[4][4], bw[8][2];
#pragma unroll
            for (int mi = 0; mi < 4; ++mi)
                ldsm4(av[mi], aA + (uint32_t)(mi * 16 * 32));
#pragma unroll
            for (int np = 0; np < 4; ++np) {
                uint32_t r4[4];
                ldsm4(r4, bW + (uint32_t)(np * 16 * 32));
                bw[2 * np][0] = r4[0]; bw[2 * np][1] = r4[1];
                bw[2 * np + 1][0] = r4[2]; bw[2 * np + 1][1] = r4[3];
            }
#pragma unroll
            for (int mi = 0; mi < 4; ++mi)
#pragma unroll
                for (int ni = 0; ni < 8; ++ni)
                    mma16816(acc[mi][ni], av[mi], bw[ni]);
        }
        __syncthreads();
    }
}

// ---------------------------------------------------------------------------
// 3a) keyp GEMM: no C store — epilogue reduces {ssk, cr, ssq} per row
// ---------------------------------------------------------------------------
__global__ void __launch_bounds__(256, 1) gemm_keyp(
    const float* __restrict__ bk, const float* __restrict__ hid,
    const float* __restrict__ n1w, const float* __restrict__ n2w)
{
    extern __shared__ __align__(1024) char smem[];
    const uint32_t sbase = smem_to_u32(smem);
    const int tid = threadIdx.x, wid = tid >> 5, lane = tid & 31;
    const int m0 = blockIdx.y * TILE_M;
    const int n0 = blockIdx.x * TILE_N;      // 0..3840
    const int wm = wid & 1, wn = wid >> 1;

    float acc[4][8][4];
    gemm_mainloop(smem, sbase, m0, n0, tid, wid, lane, wm, wn, acc);

    // epilogue: reuse smem
    float* w12s = (float*)smem;               // 256 floats
    float* bks  = (float*)(smem) + 256;       // 256 floats
    float* sred = (float*)(smem) + 512;       // [3][128][4] = 1536 floats
    w12s[tid] = n1w[n0 + tid] * n2w[n0 + tid];
    bks[tid]  = bk[n0 + tid];
    __syncthreads();

    const int gq = lane >> 2, tg = lane & 3;
    float pssk[8], pcr[8], pssq[8];
#pragma unroll
    for (int i = 0; i < 8; ++i) { pssk[i] = 0.f; pcr[i] = 0.f; pssq[i] = 0.f; }

#pragma unroll
    for (int mi = 0; mi < 4; ++mi) {
#pragma unroll
        for (int half = 0; half < 2; ++half) {
            int row = m0 + wm * 64 + mi * 16 + gq + half * 8;
            const float* hrow = hid + (size_t)row * CD + n0;
            int s8 = mi * 2 + half;
#pragma unroll
            for (int ni = 0; ni < 8; ++ni) {
                int cl = wn * 64 + ni * 8 + tg * 2;
                float2 h = *(const float2*)&hrow[cl];
                float w0 = w12s[cl], w1 = w12s[cl + 1];
                float k0 = acc[mi][ni][half * 2 + 0] + bks[cl];
                float k1 = acc[mi][ni][half * 2 + 1] + bks[cl + 1];
                pssk[s8] += k0 * k0 + k1 * k1;
                pcr[s8]  += k0 * h.x * w0 + k1 * h.y * w1;
                pssq[s8] += h.x * h.x + h.y * h.y;
            }
        }
    }
    // reduce over tg (4 lanes)
#pragma unroll
    for (int i = 0; i < 8; ++i) {
        pssk[i] += __shfl_xor_sync(0xffffffffu, pssk[i], 1);
        pssk[i] += __shfl_xor_sync(0xffffffffu, pssk[i], 2);
        pcr[i]  += __shfl_xor_sync(0xffffffffu, pcr[i], 1);
        pcr[i]  += __shfl_xor_sync(0xffffffffu, pcr[i], 2);
        pssq[i] += __shfl_xor_sync(0xffffffffu, pssq[i], 1);
        pssq[i] += __shfl_xor_sync(0xffffffffu, pssq[i], 2);
    }
    if (tg == 0) {
#pragma unroll
        for (int mi = 0; mi < 4; ++mi)
#pragma unroll
            for (int half = 0; half < 2; ++half) {
                int rl = wm * 64 + mi * 16 + gq + half * 8;
                int s8 = mi * 2 + half;
                sred[0 * 512 + rl * 4 + wn] = pssk[s8];
                sred[1 * 512 + rl * 4 + wn] = pcr[s8];
                sred[2 * 512 + rl * 4 + wn] = pssq[s8];
            }
    }
    __syncthreads();
    if (tid < 128) {
        size_t base = ((size_t)(m0 + tid) * 16 + blockIdx.x) * 3;
#pragma unroll
        for (int m = 0; m < 3; ++m) {
            float s = sred[m * 512 + tid * 4 + 0] + sred[m * 512 + tid * 4 + 1] +
                      sred[m * 512 + tid * 4 + 2] + sred[m * 512 + tid * 4 + 3];
            g_partK[base + m] = s;
        }
    }
}

// ---------------------------------------------------------------------------
// 3b) vproj GEMM: store vpb = acc + bv, reduce sv = sum vpb^2 per row
// ---------------------------------------------------------------------------
__global__ void __launch_bounds__(256, 1) gemm_vproj(const float* __restrict__ bv)
{
    extern __shared__ __align__(1024) char smem[];
    const uint32_t sbase = smem_to_u32(smem);
    const int tid = threadIdx.x, wid = tid >> 5, lane = tid & 31;
    const int m0 = blockIdx.y * TILE_M;
    const int c0 = blockIdx.x * TILE_N;      // 0..1792 (vproj cols)
    const int wm = wid & 1, wn = wid >> 1;

    float acc[4][8][4];
    gemm_mainloop(smem, sbase, m0, 4096 + c0, tid, wid, lane, wm, wn, acc);

    float* bvs  = (float*)smem;               // 256
    float* sred = (float*)(smem) + 256;       // [128][4]
    bvs[tid] = bv[c0 + tid];
    __syncthreads();

    const int gq = lane >> 2, tg = lane & 3;
    float psv[8];
#pragma unroll
    for (int i = 0; i < 8; ++i) psv[i] = 0.f;

#pragma unroll
    for (int mi = 0; mi < 4; ++mi) {
#pragma unroll
        for (int half = 0; half < 2; ++half) {
            int row = m0 + wm * 64 + mi * 16 + gq + half * 8;
            int s8 = mi * 2 + half;
            float* vrow = g_vpb + (size_t)row * D_SZ + c0;
#pragma unroll
            for (int ni = 0; ni < 8; ++ni) {
                int cl = wn * 64 + ni * 8 + tg * 2;
                float v0 = acc[mi][ni][half * 2 + 0] + bvs[cl];
                float v1 = acc[mi][ni][half * 2 + 1] + bvs[cl + 1];
                psv[s8] += v0 * v0 + v1 * v1;
                float2 o; o.x = v0; o.y = v1;
                *(float2*)&vrow[cl] = o;
            }
        }
    }
#pragma unroll
    for (int i = 0; i < 8; ++i) {
        psv[i] += __shfl_xor_sync(0xffffffffu, psv[i], 1);
        psv[i] += __shfl_xor_sync(0xffffffffu, psv[i], 2);
    }
    if (tg == 0) {
#pragma unroll
        for (int mi = 0; mi < 4; ++mi)
#pragma unroll
            for (int half = 0; half < 2; ++half) {
                int rl = wm * 64 + mi * 16 + gq + half * 8;
                sred[rl * 4 + wn] = psv[mi * 2 + half];
            }
    }
    __syncthreads();
    if (tid < 128) {
        float s = sred[tid * 4 + 0] + sred[tid * 4 + 1] +
                  sred[tid * 4 + 2] + sred[tid * 4 + 3];
        g_partV[(size_t)(m0 + tid) * 8 + blockIdx.x] = s;
    }
}

// ---------------------------------------------------------------------------
// 4) rowstats: fold partials -> per-row {gate0, gate1, q0, q1}
// ---------------------------------------------------------------------------
__global__ void __launch_bounds__(256) rowstats()
{
    int r = blockIdx.x * 256 + threadIdx.x;
    const float* pk = g_partK + (size_t)r * 16 * 3;
    float ssk[2] = {0.f, 0.f}, cr[2] = {0.f, 0.f}, ssq[2] = {0.f, 0.f};
#pragma unroll
    for (int bx = 0; bx < 16; ++bx) {
        int gg = bx >> 3;
        ssk[gg] += pk[bx * 3 + 0];
        cr[gg]  += pk[bx * 3 + 1];
        ssq[gg] += pk[bx * 3 + 2];
    }
    const float* pv = g_partV + (size_t)r * 8;
    float sv = 0.f;
#pragma unroll
    for (int bx = 0; bx < 8; ++bx) sv += pv[bx];

    const float invD = 1.0f / 2048.0f;
    const float invSqrtD = 0.022097086912079610f;
    float4 rs;
    float gate[2], q[2];
#pragma unroll
    for (int gg = 0; gg < 2; ++gg) {
        float rsk = rsqrtf(ssk[gg] * invD + EPS_DEF);
        float rsq = rsqrtf(ssq[gg] * invD + EPS_DEF);
        float gt  = rsk * rsq * cr[gg] * invSqrtD;
        float sg  = (gt > 0.f) ? 1.f : ((gt < 0.f) ? -1.f : 0.f);
        float sq  = sqrtf(fmaxf(fabsf(gt), 1e-6f)) * sg;
        gate[gg] = 1.f / (1.f + expf(-sq));
        float inv = rsqrtf(gate[gg] * gate[gg] * sv * invD + EPS_SC);
        q[gg] = gate[gg] * inv;
    }
    rs.x = gate[0]; rs.y = gate[1]; rs.z = q[0]; rs.w = q[1];
    g_rs[r] = rs;
}

// ---------------------------------------------------------------------------
// 5) fused conv + output + cache: out = gate*vpb + silu(conv(xn)), xn on the fly
// ---------------------------------------------------------------------------
__global__ void __launch_bounds__(256) conv_out(
    const float* __restrict__ cw, const float* __restrict__ scw,
    float* __restrict__ out)
{
    int idx = blockIdx.x * blockDim.x + threadIdx.x;
    int c = idx & (CD - 1);
    int r = idx >> 12;
    int l = r & (L_SZ - 1);
    int gg = c >> 11;
    int d  = c & (D_SZ - 1);

    float4 w = *(const float4*)(cw + c * 4);
    float sc = scw[c];

    const float* vp = g_vpb + (size_t)r * D_SZ + d;
    float4 rs = g_rs[r];
    float gate = gg ? rs.y : rs.x;
    float q    = gg ? rs.w : rs.z;

    float vown = vp[0];
    float xn_own = vown * q * sc;
    float acc = w.w * xn_own;
    if (l >= 3) {
        float4 rs3 = g_rs[r - 3];
        acc += w.z * vp[-3 * D_SZ] * (gg ? rs3.w : rs3.z) * sc;
    }
    if (l >= 6) {
        float4 rs6 = g_rs[r - 6];
        acc += w.y * vp[-6 * D_SZ] * (gg ? rs6.w : rs6.z) * sc;
    }
    if (l >= 9) {
        float4 rs9 = g_rs[r - 9];
        acc += w.x * vp[-9 * D_SZ] * (gg ? rs9.w : rs9.z) * sc;
    }
    float y = acc / (1.f + expf(-acc));
    out[idx] = gate * vown + y;

    if (l >= L_SZ - PAD) {
        int j = l - (L_SZ - PAD);
        int b = r >> 11;
        size_t cbase = OUT_ELEMS + (size_t)b * CD * PAD;
        out[cbase + (size_t)c * PAD + j] = xn_own;
    }
}

// ---------------------------------------------------------------------------
// launch
// ---------------------------------------------------------------------------
extern "C" void kernel_launch(void* const* d_in, const int* in_sizes, int n_in,
                              void* d_out, int out_size)
{
    const float* hid   = (const float*)d_in[0];
    const int*   ids   = (const int*)  d_in[1];
    const float* table = (const float*)d_in[2];
    const float* Wk    = (const float*)d_in[3];
    const float* bk    = (const float*)d_in[4];
    const float* Wv    = (const float*)d_in[5];
    const float* bv    = (const float*)d_in[6];
    const float* n1    = (const float*)d_in[7];
    const float* n2    = (const float*)d_in[8];
    const float* cw    = (const float*)d_in[9];
    const float* scw   = (const float*)d_in[10];
    float* out = (float*)d_out;

    cudaFuncSetAttribute(gemm_keyp, cudaFuncAttributeMaxDynamicSharedMemorySize,
                         SMEM_TOTAL);
    cudaFuncSetAttribute(gemm_vproj, cudaFuncAttributeMaxDynamicSharedMemorySize,
                         SMEM_TOTAL);

    convert_w<<<(NTOT * E_SZ / 4) / 256, 256>>>(Wk, Wv);
    gather_h<<<ROWS, 256>>>(ids, table);
    gemm_keyp<<<dim3(CD / TILE_N, ROWS / TILE_M), 256, SMEM_TOTAL>>>(bk, hid, n1, n2);
    gemm_vproj<<<dim3(D_SZ / TILE_N, ROWS / TILE_M), 256, SMEM_TOTAL>>>(bv);
    rowstats<<<ROWS / 256, 256>>>();
    conv_out<<<(int)(OUT_ELEMS / 256), 256>>>(cw, scw, out);
}

// round 8
// speedup vs baseline: 4.6159x; 1.0735x over previous
#include <cuda_runtime.h>
#include <cuda_fp16.h>
#include <math.h>
#include <stdint.h>

// ---------------------------------------------------------------------------
// Problem constants
// ---------------------------------------------------------------------------
#define B_SZ 4
#define L_SZ 2048
#define G_SZ 2
#define D_SZ 2048
#define H_SZ 16
#define DE_SZ 64
#define E_SZ 1024
#define N_SZ 32768
#define ROWS (B_SZ * L_SZ)  // 8192
#define CD (G_SZ * D_SZ)    // 4096
#define NTOT 6144
#define PAD 9
#define OUT_ELEMS ((size_t)ROWS * CD)
#define EPS_DEF 1.1920928955078125e-7f
#define EPS_SC 1e-5f

#define TILE_M 128
#define TILE_N 128
#define BK 32
#define NITER (E_SZ / BK)      // 32
#define STAGE_BYTES 16384      // A 8K | W 8K
#define NSTAGE 4
#define SMEM_TOTAL (NSTAGE * STAGE_BYTES) // 65536
#define NBLK_K 32              // CD / TILE_N
#define NBLK_V 16              // D_SZ / TILE_N

// ---------------------------------------------------------------------------
// Scratch
// ---------------------------------------------------------------------------
__device__ __half g_ea[(size_t)ROWS * E_SZ];
__device__ __half g_wh[(size_t)NTOT * E_SZ];      // rows 0..4095 Wk, 4096.. Wv
__device__ float  g_vpb[(size_t)ROWS * D_SZ];     // vproj + bv
__device__ float  g_partK[(size_t)ROWS * NBLK_K * 3];
__device__ float  g_partV[(size_t)ROWS * NBLK_V];
__device__ float4 g_rs[ROWS];                     // {gate0, gate1, q0, q1}

// ---------------------------------------------------------------------------
// PTX helpers
// ---------------------------------------------------------------------------
__device__ __forceinline__ uint32_t smem_to_u32(const void* p) {
    uint32_t a;
    asm("{ .reg .u64 t; cvta.to.shared.u64 t, %1; cvt.u32.u64 %0, t; }"
        : "=r"(a) : "l"(p));
    return a;
}
__device__ __forceinline__ void cpasync16(uint32_t s, const void* g) {
    asm volatile("cp.async.cg.shared.global [%0], [%1], 16;" :: "r"(s), "l"(g));
}
#define CP_COMMIT() asm volatile("cp.async.commit_group;" ::: "memory")
#define CP_WAIT(n)  asm volatile("cp.async.wait_group %0;" :: "n"(n) : "memory")

__device__ __forceinline__ void ldsm4(uint32_t* r, uint32_t a) {
    asm volatile("ldmatrix.sync.aligned.m8n8.x4.shared.b16 {%0,%1,%2,%3}, [%4];"
        : "=r"(r[0]), "=r"(r[1]), "=r"(r[2]), "=r"(r[3]) : "r"(a));
}
__device__ __forceinline__ void mma16816(float* c, const uint32_t* a, const uint32_t* b) {
    asm volatile(
        "mma.sync.aligned.m16n8k16.row.col.f32.f16.f16.f32 "
        "{%0,%1,%2,%3}, {%4,%5,%6,%7}, {%8,%9}, {%0,%1,%2,%3};"
        : "+f"(c[0]), "+f"(c[1]), "+f"(c[2]), "+f"(c[3])
        : "r"(a[0]), "r"(a[1]), "r"(a[2]), "r"(a[3]), "r"(b[0]), "r"(b[1]));
}
__device__ __forceinline__ uint32_t sw32(uint32_t o) { return o ^ ((o >> 3) & 0x10); }

// ---------------------------------------------------------------------------
// 1) Gather emb -> fp16
// ---------------------------------------------------------------------------
__global__ void __launch_bounds__(256) gather_h(
    const int* __restrict__ ids, const float* __restrict__ table)
{
    int r = blockIdx.x, t = threadIdx.x;
    const int* idr = ids + r * H_SZ;
    int e  = t * 4;
    int h  = e >> 6;
    int de = e & 63;
    int id = idr[h];
    float4 v = *(const float4*)&table[((size_t)(h * N_SZ + id)) * DE_SZ + de];
    __half2 p0, p1;
    p0.x = __float2half_rn(v.x); p0.y = __float2half_rn(v.y);
    p1.x = __float2half_rn(v.z); p1.y = __float2half_rn(v.w);
    *(__half2*)&g_ea[(size_t)r * E_SZ + e]     = p0;
    *(__half2*)&g_ea[(size_t)r * E_SZ + e + 2] = p1;
}

// ---------------------------------------------------------------------------
// 2) Weight -> fp16
// ---------------------------------------------------------------------------
__global__ void __launch_bounds__(256) convert_w(
    const float* __restrict__ Wk, const float* __restrict__ Wv)
{
    size_t idx = ((size_t)blockIdx.x * 256 + threadIdx.x) * 4;
    size_t n = idx >> 10;
    const float* src = (n < 4096) ? (Wk + idx) : (Wv + (idx - (size_t)4096 * E_SZ));
    float4 v = *(const float4*)src;
    __half2 h0, h1;
    h0.x = __float2half_rn(v.x); h0.y = __float2half_rn(v.y);
    h1.x = __float2half_rn(v.z); h1.y = __float2half_rn(v.w);
    *(__half2*)&g_wh[idx]     = h0;
    *(__half2*)&g_wh[idx + 2] = h1;
}

// ---------------------------------------------------------------------------
// 3) Merged fp16 GEMM, 128x128 tiles, 2 CTAs/SM.
//    blockIdx.x < 32 -> keyp (gate reductions), else -> vproj (store + sv)
// ---------------------------------------------------------------------------
__global__ void __launch_bounds__(256, 2) gemm_fused(
    const float* __restrict__ bk, const float* __restrict__ bv,
    const float* __restrict__ hid,
    const float* __restrict__ n1w, const float* __restrict__ n2w)
{
    extern __shared__ __align__(1024) char smem[];
    const uint32_t sbase = smem_to_u32(smem);
    const int tid = threadIdx.x, wid = tid >> 5, lane = tid & 31;
    const int bx = blockIdx.x;
    const int m0 = blockIdx.y * TILE_M;
    const int n0w = bx * TILE_N;   // weight row offset (0..6143)
    const int wm = wid & 1, wn = wid >> 1;   // warp 64x32

    // ---- fill: 1024 16B units per stage, 4 per thread ----
    auto fill = [&](int kt, int s) {
        const uint32_t st = sbase + (uint32_t)s * STAGE_BYTES;
        const int kb = kt * BK;
#pragma unroll
        for (int i = 0; i < 4; ++i) {
            int u = tid + i * 256;
            int isW = (u >= 512);
            int v = u & 511;
            int r = v >> 2, q = v & 3;
            uint32_t a = st + isW * 8192 + (q >> 1) * 4096 +
                         sw32((uint32_t)(r * 32 + (q & 1) * 16));
            const __half* gp = isW ? (g_wh + (size_t)(n0w + r) * E_SZ + kb + q * 8)
                                   : (g_ea + (size_t)(m0 + r) * E_SZ + kb + q * 8);
            cpasync16(a, gp);
        }
    };

    float acc[4][4][4];
#pragma unroll
    for (int mi = 0; mi < 4; ++mi)
#pragma unroll
        for (int ni = 0; ni < 4; ++ni)
#pragma unroll
            for (int j = 0; j < 4; ++j) acc[mi][ni][j] = 0.f;

    fill(0, 0); CP_COMMIT();
    fill(1, 1); CP_COMMIT();
    fill(2, 2); CP_COMMIT();

    const uint32_t offA = sw32((uint32_t)((wm * 64 + (lane & 15)) * 32 + (lane >> 4) * 16));
    const uint32_t offB = sw32((uint32_t)((wn * 32 + ((lane >> 4) << 3) + (lane & 7)) * 32 +
                                          ((lane >> 3) & 1) * 16));

    for (int it = 0; it < NITER; ++it) {
        CP_WAIT(2);
        __syncthreads();
        if (it + 3 < NITER) { fill(it + 3, (it + 3) % NSTAGE); CP_COMMIT(); }

        const uint32_t st = sbase + (uint32_t)(it % NSTAGE) * STAGE_BYTES;
#pragma unroll
        for (int ch = 0; ch < 2; ++ch) {
            const uint32_t aA = st + ch * 4096 + offA;
            const uint32_t bW = st + 8192 + ch * 4096 + offB;
            uint32_t av[4][4], bw[4][2];
#pragma unroll
            for (int mi = 0; mi < 4; ++mi)
                ldsm4(av[mi], aA + (uint32_t)(mi * 16 * 32));
#pragma unroll
            for (int np = 0; np < 2; ++np) {
                uint32_t r4[4];
                ldsm4(r4, bW + (uint32_t)(np * 16 * 32));
                bw[2 * np][0] = r4[0]; bw[2 * np][1] = r4[1];
                bw[2 * np + 1][0] = r4[2]; bw[2 * np + 1][1] = r4[3];
            }
#pragma unroll
            for (int mi = 0; mi < 4; ++mi)
#pragma unroll
                for (int ni = 0; ni < 4; ++ni)
                    mma16816(acc[mi][ni], av[mi], bw[ni]);
        }
        __syncthreads();
    }

    const int gq = lane >> 2, tg = lane & 3;

    if (bx < NBLK_K) {
        // ---- keyp epilogue: reduce {ssk, cr, ssq} ----
        const int n0 = bx * TILE_N;
        float* w12s = (float*)smem;               // 128
        float* bks  = (float*)(smem) + 128;       // 128
        float* sred = (float*)(smem) + 256;       // [3][128][4]
        if (tid < 128) {
            w12s[tid] = n1w[n0 + tid] * n2w[n0 + tid];
            bks[tid]  = bk[n0 + tid];
        }
        __syncthreads();

        float pssk[8], pcr[8], pssq[8];
#pragma unroll
        for (int i = 0; i < 8; ++i) { pssk[i] = 0.f; pcr[i] = 0.f; pssq[i] = 0.f; }

#pragma unroll
        for (int mi = 0; mi < 4; ++mi) {
#pragma unroll
            for (int half = 0; half < 2; ++half) {
                int row = m0 + wm * 64 + mi * 16 + gq + half * 8;
                const float* hrow = hid + (size_t)row * CD + n0;
                int s8 = mi * 2 + half;
#pragma unroll
                for (int ni = 0; ni < 4; ++ni) {
                    int cl = wn * 32 + ni * 8 + tg * 2;
                    float2 h = *(const float2*)&hrow[cl];
                    float k0 = acc[mi][ni][half * 2 + 0] + bks[cl];
                    float k1 = acc[mi][ni][half * 2 + 1] + bks[cl + 1];
                    pssk[s8] += k0 * k0 + k1 * k1;
                    pcr[s8]  += k0 * h.x * w12s[cl] + k1 * h.y * w12s[cl + 1];
                    pssq[s8] += h.x * h.x + h.y * h.y;
                }
            }
        }
#pragma unroll
        for (int i = 0; i < 8; ++i) {
            pssk[i] += __shfl_xor_sync(0xffffffffu, pssk[i], 1);
            pssk[i] += __shfl_xor_sync(0xffffffffu, pssk[i], 2);
            pcr[i]  += __shfl_xor_sync(0xffffffffu, pcr[i], 1);
            pcr[i]  += __shfl_xor_sync(0xffffffffu, pcr[i], 2);
            pssq[i] += __shfl_xor_sync(0xffffffffu, pssq[i], 1);
            pssq[i] += __shfl_xor_sync(0xffffffffu, pssq[i], 2);
        }
        if (tg == 0) {
#pragma unroll
            for (int mi = 0; mi < 4; ++mi)
#pragma unroll
                for (int half = 0; half < 2; ++half) {
                    int rl = wm * 64 + mi * 16 + gq + half * 8;
                    int s8 = mi * 2 + half;
                    sred[0 * 512 + rl * 4 + wn] = pssk[s8];
                    sred[1 * 512 + rl * 4 + wn] = pcr[s8];
                    sred[2 * 512 + rl * 4 + wn] = pssq[s8];
                }
        }
        __syncthreads();
        if (tid < 128) {
            size_t base = ((size_t)(m0 + tid) * NBLK_K + bx) * 3;
#pragma unroll
            for (int m = 0; m < 3; ++m) {
                float s = sred[m * 512 + tid * 4 + 0] + sred[m * 512 + tid * 4 + 1] +
                          sred[m * 512 + tid * 4 + 2] + sred[m * 512 + tid * 4 + 3];
                g_partK[base + m] = s;
            }
        }
    } else {
        // ---- vproj epilogue: store vpb + reduce sv ----
        const int c0 = (bx - NBLK_K) * TILE_N;
        float* bvs  = (float*)smem;               // 128
        float* sred = (float*)(smem) + 128;       // [128][4]
        if (tid < 128) bvs[tid] = bv[c0 + tid];
        __syncthreads();

        float psv[8];
#pragma unroll
        for (int i = 0; i < 8; ++i) psv[i] = 0.f;

#pragma unroll
        for (int mi = 0; mi < 4; ++mi) {
#pragma unroll
            for (int half = 0; half < 2; ++half) {
                int row = m0 + wm * 64 + mi * 16 + gq + half * 8;
                int s8 = mi * 2 + half;
                float* vrow = g_vpb + (size_t)row * D_SZ + c0;
#pragma unroll
                for (int ni = 0; ni < 4; ++ni) {
                    int cl = wn * 32 + ni * 8 + tg * 2;
                    float v0 = acc[mi][ni][half * 2 + 0] + bvs[cl];
                    float v1 = acc[mi][ni][half * 2 + 1] + bvs[cl + 1];
                    psv[s8] += v0 * v0 + v1 * v1;
                    float2 o; o.x = v0; o.y = v1;
                    *(float2*)&vrow[cl] = o;
                }
            }
        }
#pragma unroll
        for (int i = 0; i < 8; ++i) {
            psv[i] += __shfl_xor_sync(0xffffffffu, psv[i], 1);
            psv[i] += __shfl_xor_sync(0xffffffffu, psv[i], 2);
        }
        if (tg == 0) {
#pragma unroll
            for (int mi = 0; mi < 4; ++mi)
#pragma unroll
                for (int half = 0; half < 2; ++half) {
                    int rl = wm * 64 + mi * 16 + gq + half * 8;
                    sred[rl * 4 + wn] = psv[mi * 2 + half];
                }
        }
        __syncthreads();
        if (tid < 128) {
            float s = sred[tid * 4 + 0] + sred[tid * 4 + 1] +
                      sred[tid * 4 + 2] + sred[tid * 4 + 3];
            g_partV[(size_t)(m0 + tid) * NBLK_V + (bx - NBLK_K)] = s;
        }
    }
}

// ---------------------------------------------------------------------------
// 4) rowstats: fold partials -> per-row {gate0, gate1, q0, q1}
// ---------------------------------------------------------------------------
__global__ void __launch_bounds__(256) rowstats()
{
    int r = blockIdx.x * 256 + threadIdx.x;
    const float* pk = g_partK + (size_t)r * NBLK_K * 3;
    float ssk[2] = {0.f, 0.f}, cr[2] = {0.f, 0.f}, ssq[2] = {0.f, 0.f};
#pragma unroll
    for (int bx = 0; bx < NBLK_K; ++bx) {
        int gg = bx >> 4;
        ssk[gg] += pk[bx * 3 + 0];
        cr[gg]  += pk[bx * 3 + 1];
        ssq[gg] += pk[bx * 3 + 2];
    }
    const float* pv = g_partV + (size_t)r * NBLK_V;
    float sv = 0.f;
#pragma unroll
    for (int bx = 0; bx < NBLK_V; ++bx) sv += pv[bx];

    const float invD = 1.0f / 2048.0f;
    const float invSqrtD = 0.022097086912079610f;
    float4 rs;
    float gate[2], q[2];
#pragma unroll
    for (int gg = 0; gg < 2; ++gg) {
        float rsk = rsqrtf(ssk[gg] * invD + EPS_DEF);
        float rsq = rsqrtf(ssq[gg] * invD + EPS_DEF);
        float gt  = rsk * rsq * cr[gg] * invSqrtD;
        float sg  = (gt > 0.f) ? 1.f : ((gt < 0.f) ? -1.f : 0.f);
        float sq  = sqrtf(fmaxf(fabsf(gt), 1e-6f)) * sg;
        gate[gg] = 1.f / (1.f + expf(-sq));
        float inv = rsqrtf(gate[gg] * gate[gg] * sv * invD + EPS_SC);
        q[gg] = gate[gg] * inv;
    }
    rs.x = gate[0]; rs.y = gate[1]; rs.z = q[0]; rs.w = q[1];
    g_rs[r] = rs;
}

// ---------------------------------------------------------------------------
// 5) fused conv + output + cache
// ---------------------------------------------------------------------------
__global__ void __launch_bounds__(256) conv_out(
    const float* __restrict__ cw, const float* __restrict__ scw,
    float* __restrict__ out)
{
    int idx = blockIdx.x * blockDim.x + threadIdx.x;
    int c = idx & (CD - 1);
    int r = idx >> 12;
    int l = r & (L_SZ - 1);
    int gg = c >> 11;
    int d  = c & (D_SZ - 1);

    float4 w = *(const float4*)(cw + c * 4);
    float sc = scw[c];

    const float* vp = g_vpb + (size_t)r * D_SZ + d;
    float4 rs = g_rs[r];
    float gate = gg ? rs.y : rs.x;
    float q    = gg ? rs.w : rs.z;

    float vown = vp[0];
    float xn_own = vown * q * sc;
    float acc = w.w * xn_own;
    if (l >= 3) {
        float4 rs3 = g_rs[r - 3];
        acc += w.z * vp[-3 * D_SZ] * (gg ? rs3.w : rs3.z) * sc;
    }
    if (l >= 6) {
        float4 rs6 = g_rs[r - 6];
        acc += w.y * vp[-6 * D_SZ] * (gg ? rs6.w : rs6.z) * sc;
    }
    if (l >= 9) {
        float4 rs9 = g_rs[r - 9];
        acc += w.x * vp[-9 * D_SZ] * (gg ? rs9.w : rs9.z) * sc;
    }
    float y = acc / (1.f + expf(-acc));
    out[idx] = gate * vown + y;

    if (l >= L_SZ - PAD) {
        int j = l - (L_SZ - PAD);
        int b = r >> 11;
        size_t cbase = OUT_ELEMS + (size_t)b * CD * PAD;
        out[cbase + (size_t)c * PAD + j] = xn_own;
    }
}

// ---------------------------------------------------------------------------
// launch
// ---------------------------------------------------------------------------
extern "C" void kernel_launch(void* const* d_in, const int* in_sizes, int n_in,
                              void* d_out, int out_size)
{
    const float* hid   = (const float*)d_in[0];
    const int*   ids   = (const int*)  d_in[1];
    const float* table = (const float*)d_in[2];
    const float* Wk    = (const float*)d_in[3];
    const float* bk    = (const float*)d_in[4];
    const float* Wv    = (const float*)d_in[5];
    const float* bv    = (const float*)d_in[6];
    const float* n1    = (const float*)d_in[7];
    const float* n2    = (const float*)d_in[8];
    const float* cw    = (const float*)d_in[9];
    const float* scw   = (const float*)d_in[10];
    float* out = (float*)d_out;

    cudaFuncSetAttribute(gemm_fused, cudaFuncAttributeMaxDynamicSharedMemorySize,
                         SMEM_TOTAL);

    convert_w<<<(NTOT * E_SZ / 4) / 256, 256>>>(Wk, Wv);
    gather_h<<<ROWS, 256>>>(ids, table);
    gemm_fused<<<dim3(NTOT / TILE_N, ROWS / TILE_M), 256, SMEM_TOTAL>>>(
        bk, bv, hid, n1, n2);
    rowstats<<<ROWS / 256, 256>>>();
    conv_out<<<(int)(OUT_ELEMS / 256), 256>>>(cw, scw, out);
}

// round 9
// speedup vs baseline: 5.0730x; 1.0990x over previous
#include <cuda_runtime.h>
#include <cuda_fp16.h>
#include <math.h>
#include <stdint.h>

// ---------------------------------------------------------------------------
// Problem constants
// ---------------------------------------------------------------------------
#define B_SZ 4
#define L_SZ 2048
#define G_SZ 2
#define D_SZ 2048
#define H_SZ 16
#define DE_SZ 64
#define E_SZ 1024
#define N_SZ 32768
#define ROWS (B_SZ * L_SZ)  // 8192
#define CD (G_SZ * D_SZ)    // 4096
#define NTOT 6144
#define PAD 9
#define OUT_ELEMS ((size_t)ROWS * CD)
#define EPS_DEF 1.1920928955078125e-7f
#define EPS_SC 1e-5f

#define TILE_M 128
#define TILE_N 128
#define BK 32
#define NITER (E_SZ / BK)      // 32
#define STAGE_BYTES 16384      // A 8K | W 8K
#define NSTAGE 4
#define SMEM_TOTAL (NSTAGE * STAGE_BYTES) // 65536
#define NBLK_K 32              // CD / TILE_N
#define NBLK_V 16              // D_SZ / TILE_N
#define CONVW_BLOCKS ((NTOT * E_SZ / 4) / 256) // 6144

// ---------------------------------------------------------------------------
// Scratch
// ---------------------------------------------------------------------------
__device__ __half g_ea[(size_t)ROWS * E_SZ];
__device__ __half g_wh[(size_t)NTOT * E_SZ];      // rows 0..4095 Wk, 4096.. Wv
__device__ float  g_vpb[(size_t)ROWS * D_SZ];     // vproj + bv
__device__ float  g_partK[3 * NBLK_K * (size_t)ROWS]; // [m][blk][row] coalesced
__device__ float  g_partV[NBLK_V * (size_t)ROWS];     // [blk][row]
__device__ float4 g_rs[ROWS];                     // {gate0, gate1, q0, q1}

// ---------------------------------------------------------------------------
// PTX helpers
// ---------------------------------------------------------------------------
__device__ __forceinline__ uint32_t smem_to_u32(const void* p) {
    uint32_t a;
    asm("{ .reg .u64 t; cvta.to.shared.u64 t, %1; cvt.u32.u64 %0, t; }"
        : "=r"(a) : "l"(p));
    return a;
}
__device__ __forceinline__ void cpasync16(uint32_t s, const void* g) {
    asm volatile("cp.async.cg.shared.global [%0], [%1], 16;" :: "r"(s), "l"(g));
}
#define CP_COMMIT() asm volatile("cp.async.commit_group;" ::: "memory")
#define CP_WAIT(n)  asm volatile("cp.async.wait_group %0;" :: "n"(n) : "memory")

__device__ __forceinline__ void ldsm4(uint32_t* r, uint32_t a) {
    asm volatile("ldmatrix.sync.aligned.m8n8.x4.shared.b16 {%0,%1,%2,%3}, [%4];"
        : "=r"(r[0]), "=r"(r[1]), "=r"(r[2]), "=r"(r[3]) : "r"(a));
}
__device__ __forceinline__ void mma16816(float* c, const uint32_t* a, const uint32_t* b) {
    asm volatile(
        "mma.sync.aligned.m16n8k16.row.col.f32.f16.f16.f32 "
        "{%0,%1,%2,%3}, {%4,%5,%6,%7}, {%8,%9}, {%0,%1,%2,%3};"
        : "+f"(c[0]), "+f"(c[1]), "+f"(c[2]), "+f"(c[3])
        : "r"(a[0]), "r"(a[1]), "r"(a[2]), "r"(a[3]), "r"(b[0]), "r"(b[1]));
}
__device__ __forceinline__ uint32_t sw32(uint32_t o) { return o ^ ((o >> 3) & 0x10); }

// ---------------------------------------------------------------------------
// 1) prep: blocks [0, ROWS) gather emb->fp16; blocks [ROWS, +CONVW) W->fp16
// ---------------------------------------------------------------------------
__global__ void __launch_bounds__(256) prep(
    const int* __restrict__ ids, const float* __restrict__ table,
    const float* __restrict__ Wk, const float* __restrict__ Wv)
{
    int blk = blockIdx.x;
    int t = threadIdx.x;
    if (blk < ROWS) {
        int r = blk;
        const int* idr = ids + r * H_SZ;
        int e  = t * 4;
        int h  = e >> 6;
        int de = e & 63;
        int id = idr[h];
        float4 v = *(const float4*)&table[((size_t)(h * N_SZ + id)) * DE_SZ + de];
        __half2 p0, p1;
        p0.x = __float2half_rn(v.x); p0.y = __float2half_rn(v.y);
        p1.x = __float2half_rn(v.z); p1.y = __float2half_rn(v.w);
        *(__half2*)&g_ea[(size_t)r * E_SZ + e]     = p0;
        *(__half2*)&g_ea[(size_t)r * E_SZ + e + 2] = p1;
    } else {
        size_t idx = ((size_t)(blk - ROWS) * 256 + t) * 4;
        size_t n = idx >> 10;
        const float* src = (n < 4096) ? (Wk + idx)
                                      : (Wv + (idx - (size_t)4096 * E_SZ));
        float4 v = *(const float4*)src;
        __half2 h0, h1;
        h0.x = __float2half_rn(v.x); h0.y = __float2half_rn(v.y);
        h1.x = __float2half_rn(v.z); h1.y = __float2half_rn(v.w);
        *(__half2*)&g_wh[idx]     = h0;
        *(__half2*)&g_wh[idx + 2] = h1;
    }
}

// ---------------------------------------------------------------------------
// 2) Merged fp16 GEMM, 128x128 tiles, 2 CTAs/SM.
//    blockIdx.x < 32 -> keyp (gate reductions), else -> vproj (store + sv)
// ---------------------------------------------------------------------------
__global__ void __launch_bounds__(256, 2) gemm_fused(
    const float* __restrict__ bk, const float* __restrict__ bv,
    const float* __restrict__ hid,
    const float* __restrict__ n1w, const float* __restrict__ n2w)
{
    extern __shared__ __align__(1024) char smem[];
    const uint32_t sbase = smem_to_u32(smem);
    const int tid = threadIdx.x, wid = tid >> 5, lane = tid & 31;
    const int bx = blockIdx.x;
    const int m0 = blockIdx.y * TILE_M;
    const int n0w = bx * TILE_N;
    const int wm = wid & 1, wn = wid >> 1;   // warp 64x32

    auto fill = [&](int kt, int s) {
        const uint32_t st = sbase + (uint32_t)s * STAGE_BYTES;
        const int kb = kt * BK;
#pragma unroll
        for (int i = 0; i < 4; ++i) {
            int u = tid + i * 256;
            int isW = (u >= 512);
            int v = u & 511;
            int r = v >> 2, q = v & 3;
            uint32_t a = st + isW * 8192 + (q >> 1) * 4096 +
                         sw32((uint32_t)(r * 32 + (q & 1) * 16));
            const __half* gp = isW ? (g_wh + (size_t)(n0w + r) * E_SZ + kb + q * 8)
                                   : (g_ea + (size_t)(m0 + r) * E_SZ + kb + q * 8);
            cpasync16(a, gp);
        }
    };

    float acc[4][4][4];
#pragma unroll
    for (int mi = 0; mi < 4; ++mi)
#pragma unroll
        for (int ni = 0; ni < 4; ++ni)
#pragma unroll
            for (int j = 0; j < 4; ++j) acc[mi][ni][j] = 0.f;

    fill(0, 0); CP_COMMIT();
    fill(1, 1); CP_COMMIT();
    fill(2, 2); CP_COMMIT();

    const uint32_t offA = sw32((uint32_t)((wm * 64 + (lane & 15)) * 32 + (lane >> 4) * 16));
    const uint32_t offB = sw32((uint32_t)((wn * 32 + ((lane >> 4) << 3) + (lane & 7)) * 32 +
                                          ((lane >> 3) & 1) * 16));

    for (int it = 0; it < NITER; ++it) {
        CP_WAIT(2);
        __syncthreads();
        if (it + 3 < NITER) { fill(it + 3, (it + 3) % NSTAGE); CP_COMMIT(); }

        const uint32_t st = sbase + (uint32_t)(it % NSTAGE) * STAGE_BYTES;
#pragma unroll
        for (int ch = 0; ch < 2; ++ch) {
            const uint32_t aA = st + ch * 4096 + offA;
            const uint32_t bW = st + 8192 + ch * 4096 + offB;
            uint32_t av[4][4], bw[4][2];
#pragma unroll
            for (int mi = 0; mi < 4; ++mi)
                ldsm4(av[mi], aA + (uint32_t)(mi * 16 * 32));
#pragma unroll
            for (int np = 0; np < 2; ++np) {
                uint32_t r4[4];
                ldsm4(r4, bW + (uint32_t)(np * 16 * 32));
                bw[2 * np][0] = r4[0]; bw[2 * np][1] = r4[1];
                bw[2 * np + 1][0] = r4[2]; bw[2 * np + 1][1] = r4[3];
            }
#pragma unroll
            for (int mi = 0; mi < 4; ++mi)
#pragma unroll
                for (int ni = 0; ni < 4; ++ni)
                    mma16816(acc[mi][ni], av[mi], bw[ni]);
        }
        __syncthreads();
    }

    const int gq = lane >> 2, tg = lane & 3;

    if (bx < NBLK_K) {
        // ---- keyp epilogue: reduce {ssk, cr, ssq} ----
        const int n0 = bx * TILE_N;
        float* w12s = (float*)smem;               // 128
        float* bks  = (float*)(smem) + 128;       // 128
        float* sred = (float*)(smem) + 256;       // [3][128][4]
        if (tid < 128) {
            w12s[tid] = n1w[n0 + tid] * n2w[n0 + tid];
            bks[tid]  = bk[n0 + tid];
        }
        __syncthreads();

        float pssk[8], pcr[8], pssq[8];
#pragma unroll
        for (int i = 0; i < 8; ++i) { pssk[i] = 0.f; pcr[i] = 0.f; pssq[i] = 0.f; }

#pragma unroll
        for (int mi = 0; mi < 4; ++mi) {
#pragma unroll
            for (int half = 0; half < 2; ++half) {
                int row = m0 + wm * 64 + mi * 16 + gq + half * 8;
                const float* hrow = hid + (size_t)row * CD + n0;
                int s8 = mi * 2 + half;
#pragma unroll
                for (int ni = 0; ni < 4; ++ni) {
                    int cl = wn * 32 + ni * 8 + tg * 2;
                    float2 h = *(const float2*)&hrow[cl];
                    float k0 = acc[mi][ni][half * 2 + 0] + bks[cl];
                    float k1 = acc[mi][ni][half * 2 + 1] + bks[cl + 1];
                    pssk[s8] += k0 * k0 + k1 * k1;
                    pcr[s8]  += k0 * h.x * w12s[cl] + k1 * h.y * w12s[cl + 1];
                    pssq[s8] += h.x * h.x + h.y * h.y;
                }
            }
        }
#pragma unroll
        for (int i = 0; i < 8; ++i) {
            pssk[i] += __shfl_xor_sync(0xffffffffu, pssk[i], 1);
            pssk[i] += __shfl_xor_sync(0xffffffffu, pssk[i], 2);
            pcr[i]  += __shfl_xor_sync(0xffffffffu, pcr[i], 1);
            pcr[i]  += __shfl_xor_sync(0xffffffffu, pcr[i], 2);
            pssq[i] += __shfl_xor_sync(0xffffffffu, pssq[i], 1);
            pssq[i] += __shfl_xor_sync(0xffffffffu, pssq[i], 2);
        }
        if (tg == 0) {
#pragma unroll
            for (int mi = 0; mi < 4; ++mi)
#pragma unroll
                for (int half = 0; half < 2; ++half) {
                    int rl = wm * 64 + mi * 16 + gq + half * 8;
                    int s8 = mi * 2 + half;
                    sred[0 * 512 + rl * 4 + wn] = pssk[s8];
                    sred[1 * 512 + rl * 4 + wn] = pcr[s8];
                    sred[2 * 512 + rl * 4 + wn] = pssq[s8];
                }
        }
        __syncthreads();
        if (tid < 128) {
#pragma unroll
            for (int m = 0; m < 3; ++m) {
                float s = sred[m * 512 + tid * 4 + 0] + sred[m * 512 + tid * 4 + 1] +
                          sred[m * 512 + tid * 4 + 2] + sred[m * 512 + tid * 4 + 3];
                g_partK[((size_t)m * NBLK_K + bx) * ROWS + m0 + tid] = s;
            }
        }
    } else {
        // ---- vproj epilogue: store vpb + reduce sv ----
        const int c0 = (bx - NBLK_K) * TILE_N;
        float* bvs  = (float*)smem;               // 128
        float* sred = (float*)(smem) + 128;       // [128][4]
        if (tid < 128) bvs[tid] = bv[c0 + tid];
        __syncthreads();

        float psv[8];
#pragma unroll
        for (int i = 0; i < 8; ++i) psv[i] = 0.f;

#pragma unroll
        for (int mi = 0; mi < 4; ++mi) {
#pragma unroll
            for (int half = 0; half < 2; ++half) {
                int row = m0 + wm * 64 + mi * 16 + gq + half * 8;
                int s8 = mi * 2 + half;
                float* vrow = g_vpb + (size_t)row * D_SZ + c0;
#pragma unroll
                for (int ni = 0; ni < 4; ++ni) {
                    int cl = wn * 32 + ni * 8 + tg * 2;
                    float v0 = acc[mi][ni][half * 2 + 0] + bvs[cl];
                    float v1 = acc[mi][ni][half * 2 + 1] + bvs[cl + 1];
                    psv[s8] += v0 * v0 + v1 * v1;
                    float2 o; o.x = v0; o.y = v1;
                    *(float2*)&vrow[cl] = o;
                }
            }
        }
#pragma unroll
        for (int i = 0; i < 8; ++i) {
            psv[i] += __shfl_xor_sync(0xffffffffu, psv[i], 1);
            psv[i] += __shfl_xor_sync(0xffffffffu, psv[i], 2);
        }
        if (tg == 0) {
#pragma unroll
            for (int mi = 0; mi < 4; ++mi)
#pragma unroll
                for (int half = 0; half < 2; ++half) {
                    int rl = wm * 64 + mi * 16 + gq + half * 8;
                    sred[rl * 4 + wn] = psv[mi * 2 + half];
                }
        }
        __syncthreads();
        if (tid < 128) {
            float s = sred[tid * 4 + 0] + sred[tid * 4 + 1] +
                      sred[tid * 4 + 2] + sred[tid * 4 + 3];
            g_partV[(size_t)(bx - NBLK_K) * ROWS + m0 + tid] = s;
        }
    }
}

// ---------------------------------------------------------------------------
// 3) rowstats: fold partials (coalesced [blk][row]) -> {gate0,gate1,q0,q1}
// ---------------------------------------------------------------------------
__global__ void __launch_bounds__(256) rowstats()
{
    int r = blockIdx.x * 256 + threadIdx.x;
    float ssk[2] = {0.f, 0.f}, cr[2] = {0.f, 0.f}, ssq[2] = {0.f, 0.f};
#pragma unroll
    for (int bx = 0; bx < NBLK_K; ++bx) {
        int gg = bx >> 4;
        ssk[gg] += g_partK[((size_t)0 * NBLK_K + bx) * ROWS + r];
        cr[gg]  += g_partK[((size_t)1 * NBLK_K + bx) * ROWS + r];
        ssq[gg] += g_partK[((size_t)2 * NBLK_K + bx) * ROWS + r];
    }
    float sv = 0.f;
#pragma unroll
    for (int bx = 0; bx < NBLK_V; ++bx)
        sv += g_partV[(size_t)bx * ROWS + r];

    const float invD = 1.0f / 2048.0f;
    const float invSqrtD = 0.022097086912079610f;
    float4 rs;
    float gate[2], q[2];
#pragma unroll
    for (int gg = 0; gg < 2; ++gg) {
        float rsk = rsqrtf(ssk[gg] * invD + EPS_DEF);
        float rsq = rsqrtf(ssq[gg] * invD + EPS_DEF);
        float gt  = rsk * rsq * cr[gg] * invSqrtD;
        float sg  = (gt > 0.f) ? 1.f : ((gt < 0.f) ? -1.f : 0.f);
        float sq  = sqrtf(fmaxf(fabsf(gt), 1e-6f)) * sg;
        gate[gg] = 1.f / (1.f + expf(-sq));
        float inv = rsqrtf(gate[gg] * gate[gg] * sv * invD + EPS_SC);
        q[gg] = gate[gg] * inv;
    }
    rs.x = gate[0]; rs.y = gate[1]; rs.z = q[0]; rs.w = q[1];
    g_rs[r] = rs;
}

// ---------------------------------------------------------------------------
// 4) fused conv + output + cache, vectorized x4 along channels
// ---------------------------------------------------------------------------
__global__ void __launch_bounds__(256) conv_out(
    const float* __restrict__ cw, const float* __restrict__ scw,
    float* __restrict__ out)
{
    int v4 = blockIdx.x * blockDim.x + threadIdx.x; // float4 index
    int c = (v4 << 2) & (CD - 1);                    // channel of lane 0
    int r = v4 >> 10;                                // row (CD/4 = 1024 per row)
    int l = r & (L_SZ - 1);
    int gg = c >> 11;
    int d  = c & (D_SZ - 1);

    float4 w0 = *(const float4*)(cw + (size_t)c * 4);
    float4 w1 = *(const float4*)(cw + (size_t)(c + 1) * 4);
    float4 w2 = *(const float4*)(cw + (size_t)(c + 2) * 4);
    float4 w3 = *(const float4*)(cw + (size_t)(c + 3) * 4);
    float4 sc = *(const float4*)(scw + c);

    const float* vp = g_vpb + (size_t)r * D_SZ + d;
    float4 rs = g_rs[r];
    float gate = gg ? rs.y : rs.x;
    float q    = gg ? rs.w : rs.z;

    float4 vo = *(const float4*)vp;
    float xn0 = vo.x * q * sc.x;
    float xn1 = vo.y * q * sc.y;
    float xn2 = vo.z * q * sc.z;
    float xn3 = vo.w * q * sc.w;
    float a0 = w0.w * xn0, a1 = w1.w * xn1, a2 = w2.w * xn2, a3 = w3.w * xn3;

    if (l >= 3) {
        float4 rp = g_rs[r - 3];
        float qq = gg ? rp.w : rp.z;
        float4 vv = *(const float4*)(vp - 3 * D_SZ);
        a0 += w0.z * vv.x * qq * sc.x;
        a1 += w1.z * vv.y * qq * sc.y;
        a2 += w2.z * vv.z * qq * sc.z;
        a3 += w3.z * vv.w * qq * sc.w;
    }
    if (l >= 6) {
        float4 rp = g_rs[r - 6];
        float qq = gg ? rp.w : rp.z;
        float4 vv = *(const float4*)(vp - 6 * D_SZ);
        a0 += w0.y * vv.x * qq * sc.x;
        a1 += w1.y * vv.y * qq * sc.y;
        a2 += w2.y * vv.z * qq * sc.z;
        a3 += w3.y * vv.w * qq * sc.w;
    }
    if (l >= 9) {
        float4 rp = g_rs[r - 9];
        float qq = gg ? rp.w : rp.z;
        float4 vv = *(const float4*)(vp - 9 * D_SZ);
        a0 += w0.x * vv.x * qq * sc.x;
        a1 += w1.x * vv.y * qq * sc.y;
        a2 += w2.x * vv.z * qq * sc.z;
        a3 += w3.x * vv.w * qq * sc.w;
    }
    float4 o;
    o.x = gate * vo.x + a0 / (1.f + expf(-a0));
    o.y = gate * vo.y + a1 / (1.f + expf(-a1));
    o.z = gate * vo.z + a2 / (1.f + expf(-a2));
    o.w = gate * vo.w + a3 / (1.f + expf(-a3));
    *(float4*)&out[(size_t)r * CD + c] = o;

    if (l >= L_SZ - PAD) {
        int j = l - (L_SZ - PAD);
        int b = r >> 11;
        size_t cbase = OUT_ELEMS + (size_t)b * CD * PAD;
        out[cbase + (size_t)(c + 0) * PAD + j] = xn0;
        out[cbase + (size_t)(c + 1) * PAD + j] = xn1;
        out[cbase + (size_t)(c + 2) * PAD + j] = xn2;
        out[cbase + (size_t)(c + 3) * PAD + j] = xn3;
    }
}

// ---------------------------------------------------------------------------
// launch
// ---------------------------------------------------------------------------
extern "C" void kernel_launch(void* const* d_in, const int* in_sizes, int n_in,
                              void* d_out, int out_size)
{
    const float* hid   = (const float*)d_in[0];
    const int*   ids   = (const int*)  d_in[1];
    const float* table = (const float*)d_in[2];
    const float* Wk    = (const float*)d_in[3];
    const float* bk    = (const float*)d_in[4];
    const float* Wv    = (const float*)d_in[5];
    const float* bv    = (const float*)d_in[6];
    const float* n1    = (const float*)d_in[7];
    const float* n2    = (const float*)d_in[8];
    const float* cw    = (const float*)d_in[9];
    const float* scw   = (const float*)d_in[10];
    float* out = (float*)d_out;

    cudaFuncSetAttribute(gemm_fused, cudaFuncAttributeMaxDynamicSharedMemorySize,
                         SMEM_TOTAL);

    prep<<<ROWS + CONVW_BLOCKS, 256>>>(ids, table, Wk, Wv);
    gemm_fused<<<dim3(NTOT / TILE_N, ROWS / TILE_M), 256, SMEM_TOTAL>>>(
        bk, bv, hid, n1, n2);
    rowstats<<<ROWS / 256, 256>>>();
    conv_out<<<(int)(OUT_ELEMS / 4 / 256), 256>>>(cw, scw, out);
}

// round 10
// speedup vs baseline: 5.4156x; 1.0675x over previous
#include <cuda_runtime.h>
#include <cuda_fp16.h>
#include <math.h>
#include <stdint.h>

// ---------------------------------------------------------------------------
// Problem constants
// ---------------------------------------------------------------------------
#define B_SZ 4
#define L_SZ 2048
#define G_SZ 2
#define D_SZ 2048
#define H_SZ 16
#define DE_SZ 64
#define E_SZ 1024
#define N_SZ 32768
#define ROWS (B_SZ * L_SZ)  // 8192
#define CD (G_SZ * D_SZ)    // 4096
#define NTOT 6144
#define PAD 9
#define OUT_ELEMS ((size_t)ROWS * CD)
#define EPS_DEF 1.1920928955078125e-7f
#define EPS_SC 1e-5f

#define TILE_M 128
#define TILE_N 128
#define BK 32
#define NITER (E_SZ / BK)      // 32
#define STAGE_BYTES 16384      // A 8K | W 8K
#define NSTAGE 4
#define SMEM_TOTAL (NSTAGE * STAGE_BYTES) // 65536
#define NBLK_K 32
#define NBLK_V 16
#define CONVW_BLOCKS ((NTOT * E_SZ / 4) / 256) // 6144

#define LCH 12                 // rows per conv thread
#define NCHUNK 171             // ceil(2048/12)

// ---------------------------------------------------------------------------
// Scratch
// ---------------------------------------------------------------------------
__device__ __half g_ea[(size_t)ROWS * E_SZ];
__device__ __half g_wh[(size_t)NTOT * E_SZ];
__device__ float  g_vpb[(size_t)ROWS * D_SZ];
__device__ float  g_partK[3 * NBLK_K * (size_t)ROWS]; // [m][blk][row]
__device__ float  g_partV[NBLK_V * (size_t)ROWS];     // [blk][row]
__device__ float4 g_rs[ROWS];                         // {gate0, gate1, q0, q1}

// ---------------------------------------------------------------------------
// PTX helpers
// ---------------------------------------------------------------------------
__device__ __forceinline__ uint32_t smem_to_u32(const void* p) {
    uint32_t a;
    asm("{ .reg .u64 t; cvta.to.shared.u64 t, %1; cvt.u32.u64 %0, t; }"
        : "=r"(a) : "l"(p));
    return a;
}
__device__ __forceinline__ void cpasync16(uint32_t s, const void* g) {
    asm volatile("cp.async.cg.shared.global [%0], [%1], 16;" :: "r"(s), "l"(g));
}
#define CP_COMMIT() asm volatile("cp.async.commit_group;" ::: "memory")
#define CP_WAIT(n)  asm volatile("cp.async.wait_group %0;" :: "n"(n) : "memory")

__device__ __forceinline__ void ldsm4(uint32_t* r, uint32_t a) {
    asm volatile("ldmatrix.sync.aligned.m8n8.x4.shared.b16 {%0,%1,%2,%3}, [%4];"
        : "=r"(r[0]), "=r"(r[1]), "=r"(r[2]), "=r"(r[3]) : "r"(a));
}
__device__ __forceinline__ void mma16816(float* c, const uint32_t* a, const uint32_t* b) {
    asm volatile(
        "mma.sync.aligned.m16n8k16.row.col.f32.f16.f16.f32 "
        "{%0,%1,%2,%3}, {%4,%5,%6,%7}, {%8,%9}, {%0,%1,%2,%3};"
        : "+f"(c[0]), "+f"(c[1]), "+f"(c[2]), "+f"(c[3])
        : "r"(a[0]), "r"(a[1]), "r"(a[2]), "r"(a[3]), "r"(b[0]), "r"(b[1]));
}
__device__ __forceinline__ uint32_t sw32(uint32_t o) { return o ^ ((o >> 3) & 0x10); }

// ---------------------------------------------------------------------------
// 1) prep: gather emb->fp16 + convert W->fp16
// ---------------------------------------------------------------------------
__global__ void __launch_bounds__(256) prep(
    const int* __restrict__ ids, const float* __restrict__ table,
    const float* __restrict__ Wk, const float* __restrict__ Wv)
{
    int blk = blockIdx.x;
    int t = threadIdx.x;
    if (blk < ROWS) {
        int r = blk;
        const int* idr = ids + r * H_SZ;
        int e  = t * 4;
        int h  = e >> 6;
        int de = e & 63;
        int id = idr[h];
        float4 v = *(const float4*)&table[((size_t)(h * N_SZ + id)) * DE_SZ + de];
        __half2 p0, p1;
        p0.x = __float2half_rn(v.x); p0.y = __float2half_rn(v.y);
        p1.x = __float2half_rn(v.z); p1.y = __float2half_rn(v.w);
        *(__half2*)&g_ea[(size_t)r * E_SZ + e]     = p0;
        *(__half2*)&g_ea[(size_t)r * E_SZ + e + 2] = p1;
    } else {
        size_t idx = ((size_t)(blk - ROWS) * 256 + t) * 4;
        size_t n = idx >> 10;
        const float* src = (n < 4096) ? (Wk + idx)
                                      : (Wv + (idx - (size_t)4096 * E_SZ));
        float4 v = *(const float4*)src;
        __half2 h0, h1;
        h0.x = __float2half_rn(v.x); h0.y = __float2half_rn(v.y);
        h1.x = __float2half_rn(v.z); h1.y = __float2half_rn(v.w);
        *(__half2*)&g_wh[idx]     = h0;
        *(__half2*)&g_wh[idx + 2] = h1;
    }
}

// ---------------------------------------------------------------------------
// 2) Merged fp16 GEMM, 128x128 tiles, 2 CTAs/SM
// ---------------------------------------------------------------------------
__global__ void __launch_bounds__(256, 2) gemm_fused(
    const float* __restrict__ bk, const float* __restrict__ bv,
    const float* __restrict__ hid,
    const float* __restrict__ n1w, const float* __restrict__ n2w)
{
    extern __shared__ __align__(1024) char smem[];
    const uint32_t sbase = smem_to_u32(smem);
    const int tid = threadIdx.x, wid = tid >> 5, lane = tid & 31;
    const int bx = blockIdx.x;
    const int m0 = blockIdx.y * TILE_M;
    const int n0w = bx * TILE_N;
    const int wm = wid & 1, wn = wid >> 1;

    auto fill = [&](int kt, int s) {
        const uint32_t st = sbase + (uint32_t)s * STAGE_BYTES;
        const int kb = kt * BK;
#pragma unroll
        for (int i = 0; i < 4; ++i) {
            int u = tid + i * 256;
            int isW = (u >= 512);
            int v = u & 511;
            int r = v >> 2, q = v & 3;
            uint32_t a = st + isW * 8192 + (q >> 1) * 4096 +
                         sw32((uint32_t)(r * 32 + (q & 1) * 16));
            const __half* gp = isW ? (g_wh + (size_t)(n0w + r) * E_SZ + kb + q * 8)
                                   : (g_ea + (size_t)(m0 + r) * E_SZ + kb + q * 8);
            cpasync16(a, gp);
        }
    };

    float acc[4][4][4];
#pragma unroll
    for (int mi = 0; mi < 4; ++mi)
#pragma unroll
        for (int ni = 0; ni < 4; ++ni)
#pragma unroll
            for (int j = 0; j < 4; ++j) acc[mi][ni][j] = 0.f;

    fill(0, 0); CP_COMMIT();
    fill(1, 1); CP_COMMIT();
    fill(2, 2); CP_COMMIT();

    const uint32_t offA = sw32((uint32_t)((wm * 64 + (lane & 15)) * 32 + (lane >> 4) * 16));
    const uint32_t offB = sw32((uint32_t)((wn * 32 + ((lane >> 4) << 3) + (lane & 7)) * 32 +
                                          ((lane >> 3) & 1) * 16));

    for (int it = 0; it < NITER; ++it) {
        CP_WAIT(2);
        __syncthreads();
        if (it + 3 < NITER) { fill(it + 3, (it + 3) % NSTAGE); CP_COMMIT(); }

        const uint32_t st = sbase + (uint32_t)(it % NSTAGE) * STAGE_BYTES;
#pragma unroll
        for (int ch = 0; ch < 2; ++ch) {
            const uint32_t aA = st + ch * 4096 + offA;
            const uint32_t bW = st + 8192 + ch * 4096 + offB;
            uint32_t av[4][4], bw[4][2];
#pragma unroll
            for (int mi = 0; mi < 4; ++mi)
                ldsm4(av[mi], aA + (uint32_t)(mi * 16 * 32));
#pragma unroll
            for (int np = 0; np < 2; ++np) {
                uint32_t r4[4];
                ldsm4(r4, bW + (uint32_t)(np * 16 * 32));
                bw[2 * np][0] = r4[0]; bw[2 * np][1] = r4[1];
                bw[2 * np + 1][0] = r4[2]; bw[2 * np + 1][1] = r4[3];
            }
#pragma unroll
            for (int mi = 0; mi < 4; ++mi)
#pragma unroll
                for (int ni = 0; ni < 4; ++ni)
                    mma16816(acc[mi][ni], av[mi], bw[ni]);
        }
        __syncthreads();
    }

    const int gq = lane >> 2, tg = lane & 3;

    if (bx < NBLK_K) {
        const int n0 = bx * TILE_N;
        float* w12s = (float*)smem;
        float* bks  = (float*)(smem) + 128;
        float* sred = (float*)(smem) + 256;
        if (tid < 128) {
            w12s[tid] = n1w[n0 + tid] * n2w[n0 + tid];
            bks[tid]  = bk[n0 + tid];
        }
        __syncthreads();

        float pssk[8], pcr[8], pssq[8];
#pragma unroll
        for (int i = 0; i < 8; ++i) { pssk[i] = 0.f; pcr[i] = 0.f; pssq[i] = 0.f; }

#pragma unroll
        for (int mi = 0; mi < 4; ++mi) {
#pragma unroll
            for (int half = 0; half < 2; ++half) {
                int row = m0 + wm * 64 + mi * 16 + gq + half * 8;
                const float* hrow = hid + (size_t)row * CD + n0;
                int s8 = mi * 2 + half;
#pragma unroll
                for (int ni = 0; ni < 4; ++ni) {
                    int cl = wn * 32 + ni * 8 + tg * 2;
                    float2 h = *(const float2*)&hrow[cl];
                    float k0 = acc[mi][ni][half * 2 + 0] + bks[cl];
                    float k1 = acc[mi][ni][half * 2 + 1] + bks[cl + 1];
                    pssk[s8] += k0 * k0 + k1 * k1;
                    pcr[s8]  += k0 * h.x * w12s[cl] + k1 * h.y * w12s[cl + 1];
                    pssq[s8] += h.x * h.x + h.y * h.y;
                }
            }
        }
#pragma unroll
        for (int i = 0; i < 8; ++i) {
            pssk[i] += __shfl_xor_sync(0xffffffffu, pssk[i], 1);
            pssk[i] += __shfl_xor_sync(0xffffffffu, pssk[i], 2);
            pcr[i]  += __shfl_xor_sync(0xffffffffu, pcr[i], 1);
            pcr[i]  += __shfl_xor_sync(0xffffffffu, pcr[i], 2);
            pssq[i] += __shfl_xor_sync(0xffffffffu, pssq[i], 1);
            pssq[i] += __shfl_xor_sync(0xffffffffu, pssq[i], 2);
        }
        if (tg == 0) {
#pragma unroll
            for (int mi = 0; mi < 4; ++mi)
#pragma unroll
                for (int half = 0; half < 2; ++half) {
                    int rl = wm * 64 + mi * 16 + gq + half * 8;
                    int s8 = mi * 2 + half;
                    sred[0 * 512 + rl * 4 + wn] = pssk[s8];
                    sred[1 * 512 + rl * 4 + wn] = pcr[s8];
                    sred[2 * 512 + rl * 4 + wn] = pssq[s8];
                }
        }
        __syncthreads();
        if (tid < 128) {
#pragma unroll
            for (int m = 0; m < 3; ++m) {
                float s = sred[m * 512 + tid * 4 + 0] + sred[m * 512 + tid * 4 + 1] +
                          sred[m * 512 + tid * 4 + 2] + sred[m * 512 + tid * 4 + 3];
                g_partK[((size_t)m * NBLK_K + bx) * ROWS + m0 + tid] = s;
            }
        }
    } else {
        const int c0 = (bx - NBLK_K) * TILE_N;
        float* bvs  = (float*)smem;
        float* sred = (float*)(smem) + 128;
        if (tid < 128) bvs[tid] = bv[c0 + tid];
        __syncthreads();

        float psv[8];
#pragma unroll
        for (int i = 0; i < 8; ++i) psv[i] = 0.f;

#pragma unroll
        for (int mi = 0; mi < 4; ++mi) {
#pragma unroll
            for (int half = 0; half < 2; ++half) {
                int row = m0 + wm * 64 + mi * 16 + gq + half * 8;
                int s8 = mi * 2 + half;
                float* vrow = g_vpb + (size_t)row * D_SZ + c0;
#pragma unroll
                for (int ni = 0; ni < 4; ++ni) {
                    int cl = wn * 32 + ni * 8 + tg * 2;
                    float v0 = acc[mi][ni][half * 2 + 0] + bvs[cl];
                    float v1 = acc[mi][ni][half * 2 + 1] + bvs[cl + 1];
                    psv[s8] += v0 * v0 + v1 * v1;
                    float2 o; o.x = v0; o.y = v1;
                    *(float2*)&vrow[cl] = o;
                }
            }
        }
#pragma unroll
        for (int i = 0; i < 8; ++i) {
            psv[i] += __shfl_xor_sync(0xffffffffu, psv[i], 1);
            psv[i] += __shfl_xor_sync(0xffffffffu, psv[i], 2);
        }
        if (tg == 0) {
#pragma unroll
            for (int mi = 0; mi < 4; ++mi)
#pragma unroll
                for (int half = 0; half < 2; ++half) {
                    int rl = wm * 64 + mi * 16 + gq + half * 8;
                    sred[rl * 4 + wn] = psv[mi * 2 + half];
                }
        }
        __syncthreads();
        if (tid < 128) {
            float s = sred[tid * 4 + 0] + sred[tid * 4 + 1] +
                      sred[tid * 4 + 2] + sred[tid * 4 + 3];
            g_partV[(size_t)(bx - NBLK_K) * ROWS + m0 + tid] = s;
        }
    }
}

// ---------------------------------------------------------------------------
// 3) rowstats
// ---------------------------------------------------------------------------
__global__ void __launch_bounds__(256) rowstats()
{
    int r = blockIdx.x * 256 + threadIdx.x;
    float ssk[2] = {0.f, 0.f}, cr[2] = {0.f, 0.f}, ssq[2] = {0.f, 0.f};
#pragma unroll
    for (int bx = 0; bx < NBLK_K; ++bx) {
        int gg = bx >> 4;
        ssk[gg] += g_partK[((size_t)0 * NBLK_K + bx) * ROWS + r];
        cr[gg]  += g_partK[((size_t)1 * NBLK_K + bx) * ROWS + r];
        ssq[gg] += g_partK[((size_t)2 * NBLK_K + bx) * ROWS + r];
    }
    float sv = 0.f;
#pragma unroll
    for (int bx = 0; bx < NBLK_V; ++bx)
        sv += g_partV[(size_t)bx * ROWS + r];

    const float invD = 1.0f / 2048.0f;
    const float invSqrtD = 0.022097086912079610f;
    float4 rs;
    float gate[2], q[2];
#pragma unroll
    for (int gg = 0; gg < 2; ++gg) {
        float rsk = rsqrtf(ssk[gg] * invD + EPS_DEF);
        float rsq = rsqrtf(ssq[gg] * invD + EPS_DEF);
        float gt  = rsk * rsq * cr[gg] * invSqrtD;
        float sg  = (gt > 0.f) ? 1.f : ((gt < 0.f) ? -1.f : 0.f);
        float sq  = sqrtf(fmaxf(fabsf(gt), 1e-6f)) * sg;
        gate[gg] = 1.f / (1.f + expf(-sq));
        float inv = rsqrtf(gate[gg] * gate[gg] * sv * invD + EPS_SC);
        q[gg] = gate[gg] * inv;
    }
    rs.x = gate[0]; rs.y = gate[1]; rs.z = q[0]; rs.w = q[1];
    g_rs[r] = rs;
}

// ---------------------------------------------------------------------------
// 4) conv_out: 12 rows per thread, rolling xn window (dilation-3 causal)
//    thread -> (c4 group, batch, 12-row chunk). Warp = 32 consecutive c4.
// ---------------------------------------------------------------------------
__global__ void __launch_bounds__(256) conv_out(
    const float* __restrict__ cw, const float* __restrict__ scw,
    float* __restrict__ out)
{
    int t = blockIdx.x * blockDim.x + threadIdx.x;
    int c4 = t & 1023;            // CD/4 groups
    int chunk = t >> 10;          // 0 .. 4*171-1
    if (chunk >= B_SZ * NCHUNK) return;
    int b = chunk / NCHUNK;
    int l0 = (chunk - b * NCHUNK) * LCH;
    int cnt = (L_SZ - l0 < LCH) ? (L_SZ - l0) : LCH;

    int c = c4 << 2;
    int gg = c >> 11;
    int d  = c & (D_SZ - 1);
    int rbase = b * L_SZ;

    float4 w0 = *(const float4*)(cw + (size_t)c * 4);
    float4 w1 = *(const float4*)(cw + (size_t)(c + 1) * 4);
    float4 w2 = *(const float4*)(cw + (size_t)(c + 2) * 4);
    float4 w3 = *(const float4*)(cw + (size_t)(c + 3) * 4);
    float4 sc = *(const float4*)(scw + c);

    float4 win[LCH];
    // preload xn for l0-9 .. l0-1 into slot (l mod 12) = 12-j
#pragma unroll
    for (int j = 1; j <= 9; ++j) {
        int l = l0 - j;
        int slot = LCH - j;
        if (l >= 0) {
            int r = rbase + l;
            float4 vv = *(const float4*)(g_vpb + (size_t)r * D_SZ + d);
            float4 rp = g_rs[r];
            float q = gg ? rp.w : rp.z;
            float4 x;
            x.x = vv.x * q * sc.x; x.y = vv.y * q * sc.y;
            x.z = vv.z * q * sc.z; x.w = vv.w * q * sc.w;
            win[slot] = x;
        } else {
            win[slot] = make_float4(0.f, 0.f, 0.f, 0.f);
        }
    }

#pragma unroll
    for (int i = 0; i < LCH; ++i) {
        if (i >= cnt) break;
        int l = l0 + i;
        int r = rbase + l;
        float4 vo = *(const float4*)(g_vpb + (size_t)r * D_SZ + d);
        float4 rp = g_rs[r];
        float gate = gg ? rp.y : rp.x;
        float q    = gg ? rp.w : rp.z;
        float4 x;
        x.x = vo.x * q * sc.x; x.y = vo.y * q * sc.y;
        x.z = vo.z * q * sc.z; x.w = vo.w * q * sc.w;
        win[i] = x;

        float a0 = w0.w * x.x, a1 = w1.w * x.y, a2 = w2.w * x.z, a3 = w3.w * x.w;
        {
            float4 t3 = win[(i + 9) % LCH];   // l-3
            a0 += w0.z * t3.x; a1 += w1.z * t3.y;
            a2 += w2.z * t3.z; a3 += w3.z * t3.w;
            float4 t6 = win[(i + 6) % LCH];   // l-6
            a0 += w0.y * t6.x; a1 += w1.y * t6.y;
            a2 += w2.y * t6.z; a3 += w3.y * t6.w;
            float4 t9 = win[(i + 3) % LCH];   // l-9
            a0 += w0.x * t9.x; a1 += w1.x * t9.y;
            a2 += w2.x * t9.z; a3 += w3.x * t9.w;
        }
        float4 o;
        o.x = gate * vo.x + a0 / (1.f + expf(-a0));
        o.y = gate * vo.y + a1 / (1.f + expf(-a1));
        o.z = gate * vo.z + a2 / (1.f + expf(-a2));
        o.w = gate * vo.w + a3 / (1.f + expf(-a3));
        *(float4*)&out[(size_t)r * CD + c] = o;

        if (l >= L_SZ - PAD) {
            int j = l - (L_SZ - PAD);
            size_t cbase = OUT_ELEMS + (size_t)b * CD * PAD;
            out[cbase + (size_t)(c + 0) * PAD + j] = x.x;
            out[cbase + (size_t)(c + 1) * PAD + j] = x.y;
            out[cbase + (size_t)(c + 2) * PAD + j] = x.z;
            out[cbase + (size_t)(c + 3) * PAD + j] = x.w;
        }
    }
}

// ---------------------------------------------------------------------------
// launch
// ---------------------------------------------------------------------------
extern "C" void kernel_launch(void* const* d_in, const int* in_sizes, int n_in,
                              void* d_out, int out_size)
{
    const float* hid   = (const float*)d_in[0];
    const int*   ids   = (const int*)  d_in[1];
    const float* table = (const float*)d_in[2];
    const float* Wk    = (const float*)d_in[3];
    const float* bk    = (const float*)d_in[4];
    const float* Wv    = (const float*)d_in[5];
    const float* bv    = (const float*)d_in[6];
    const float* n1    = (const float*)d_in[7];
    const float* n2    = (const float*)d_in[8];
    const float* cw    = (const float*)d_in[9];
    const float* scw   = (const float*)d_in[10];
    float* out = (float*)d_out;

    cudaFuncSetAttribute(gemm_fused, cudaFuncAttributeMaxDynamicSharedMemorySize,
                         SMEM_TOTAL);

    prep<<<ROWS + CONVW_BLOCKS, 256>>>(ids, table, Wk, Wv);
    gemm_fused<<<dim3(NTOT / TILE_N, ROWS / TILE_M), 256, SMEM_TOTAL>>>(
        bk, bv, hid, n1, n2);
    rowstats<<<ROWS / 256, 256>>>();
    int conv_threads = 1024 * B_SZ * NCHUNK;
    conv_out<<<(conv_threads + 255) / 256, 256>>>(cw, scw, out);
}

// round 11
// speedup vs baseline: 5.5453x; 1.0240x over previous
#include <cuda_runtime.h>
#include <cuda_fp16.h>
#include <math.h>
#include <stdint.h>

// ---------------------------------------------------------------------------
// Problem constants
// ---------------------------------------------------------------------------
#define B_SZ 4
#define L_SZ 2048
#define G_SZ 2
#define D_SZ 2048
#define H_SZ 16
#define DE_SZ 64
#define E_SZ 1024
#define N_SZ 32768
#define ROWS (B_SZ * L_SZ)  // 8192
#define CD (G_SZ * D_SZ)    // 4096
#define NTOT 6144
#define PAD 9
#define OUT_ELEMS ((size_t)ROWS * CD)
#define EPS_DEF 1.1920928955078125e-7f
#define EPS_SC 1e-5f

#define TILE_M 128
#define TILE_N 128
#define BK 32
#define NITER (E_SZ / BK)      // 32
#define STAGE_BYTES 16384      // A 8K | W 8K
#define NSTAGE 4
#define SMEM_TOTAL (NSTAGE * STAGE_BYTES) // 65536
#define NBLK_K 32
#define NBLK_V 16
#define CONVW_BLOCKS ((NTOT * E_SZ / 4) / 256) // 6144

#define LCH 12                 // rows per conv thread
#define NCHUNK 171             // ceil(2048/12)

// ---------------------------------------------------------------------------
// Scratch
// ---------------------------------------------------------------------------
__device__ __half g_ea[(size_t)ROWS * E_SZ];
__device__ __half g_wh[(size_t)NTOT * E_SZ];
__device__ float  g_vpb[(size_t)ROWS * D_SZ];
__device__ float  g_partK[3 * NBLK_K * (size_t)ROWS]; // [m][blk][row]
__device__ float  g_partV[NBLK_V * (size_t)ROWS];     // [blk][row]
__device__ float4 g_rs[ROWS];                         // {gate0, gate1, q0, q1}

// ---------------------------------------------------------------------------
// PTX helpers
// ---------------------------------------------------------------------------
__device__ __forceinline__ uint32_t smem_to_u32(const void* p) {
    uint32_t a;
    asm("{ .reg .u64 t; cvta.to.shared.u64 t, %1; cvt.u32.u64 %0, t; }"
        : "=r"(a) : "l"(p));
    return a;
}
__device__ __forceinline__ void cpasync16(uint32_t s, const void* g) {
    asm volatile("cp.async.cg.shared.global [%0], [%1], 16;" :: "r"(s), "l"(g));
}
#define CP_COMMIT() asm volatile("cp.async.commit_group;" ::: "memory")
#define CP_WAIT(n)  asm volatile("cp.async.wait_group %0;" :: "n"(n) : "memory")

__device__ __forceinline__ void ldsm4(uint32_t* r, uint32_t a) {
    asm volatile("ldmatrix.sync.aligned.m8n8.x4.shared.b16 {%0,%1,%2,%3}, [%4];"
        : "=r"(r[0]), "=r"(r[1]), "=r"(r[2]), "=r"(r[3]) : "r"(a));
}
__device__ __forceinline__ void mma16816(float* c, const uint32_t* a, const uint32_t* b) {
    asm volatile(
        "mma.sync.aligned.m16n8k16.row.col.f32.f16.f16.f32 "
        "{%0,%1,%2,%3}, {%4,%5,%6,%7}, {%8,%9}, {%0,%1,%2,%3};"
        : "+f"(c[0]), "+f"(c[1]), "+f"(c[2]), "+f"(c[3])
        : "r"(a[0]), "r"(a[1]), "r"(a[2]), "r"(a[3]), "r"(b[0]), "r"(b[1]));
}
__device__ __forceinline__ uint32_t sw32(uint32_t o) { return o ^ ((o >> 3) & 0x10); }

__device__ __forceinline__ float silu_fast(float a) {
    // a * sigmoid(a) via fast ex2
    return __fdividef(a, 1.f + __expf(-a));
}

// ---------------------------------------------------------------------------
// 1) prep: gather emb->fp16 + convert W->fp16
// ---------------------------------------------------------------------------
__global__ void __launch_bounds__(256) prep(
    const int* __restrict__ ids, const float* __restrict__ table,
    const float* __restrict__ Wk, const float* __restrict__ Wv)
{
    int blk = blockIdx.x;
    int t = threadIdx.x;
    if (blk < ROWS) {
        int r = blk;
        const int* idr = ids + r * H_SZ;
        int e  = t * 4;
        int h  = e >> 6;
        int de = e & 63;
        int id = idr[h];
        float4 v = *(const float4*)&table[((size_t)(h * N_SZ + id)) * DE_SZ + de];
        __half2 p0, p1;
        p0.x = __float2half_rn(v.x); p0.y = __float2half_rn(v.y);
        p1.x = __float2half_rn(v.z); p1.y = __float2half_rn(v.w);
        *(__half2*)&g_ea[(size_t)r * E_SZ + e]     = p0;
        *(__half2*)&g_ea[(size_t)r * E_SZ + e + 2] = p1;
    } else {
        size_t idx = ((size_t)(blk - ROWS) * 256 + t) * 4;
        size_t n = idx >> 10;
        const float* src = (n < 4096) ? (Wk + idx)
                                      : (Wv + (idx - (size_t)4096 * E_SZ));
        float4 v = *(const float4*)src;
        __half2 h0, h1;
        h0.x = __float2half_rn(v.x); h0.y = __float2half_rn(v.y);
        h1.x = __float2half_rn(v.z); h1.y = __float2half_rn(v.w);
        *(__half2*)&g_wh[idx]     = h0;
        *(__half2*)&g_wh[idx + 2] = h1;
    }
}

// ---------------------------------------------------------------------------
// 2) Merged fp16 GEMM, 128x128 tiles, 2 CTAs/SM
// ---------------------------------------------------------------------------
__global__ void __launch_bounds__(256, 2) gemm_fused(
    const float* __restrict__ bk, const float* __restrict__ bv,
    const float* __restrict__ hid,
    const float* __restrict__ n1w, const float* __restrict__ n2w)
{
    extern __shared__ __align__(1024) char smem[];
    const uint32_t sbase = smem_to_u32(smem);
    const int tid = threadIdx.x, wid = tid >> 5, lane = tid & 31;
    const int bx = blockIdx.x;
    const int m0 = blockIdx.y * TILE_M;
    const int n0w = bx * TILE_N;
    const int wm = wid & 1, wn = wid >> 1;

    auto fill = [&](int kt, int s) {
        const uint32_t st = sbase + (uint32_t)s * STAGE_BYTES;
        const int kb = kt * BK;
#pragma unroll
        for (int i = 0; i < 4; ++i) {
            int u = tid + i * 256;
            int isW = (u >= 512);
            int v = u & 511;
            int r = v >> 2, q = v & 3;
            uint32_t a = st + isW * 8192 + (q >> 1) * 4096 +
                         sw32((uint32_t)(r * 32 + (q & 1) * 16));
            const __half* gp = isW ? (g_wh + (size_t)(n0w + r) * E_SZ + kb + q * 8)
                                   : (g_ea + (size_t)(m0 + r) * E_SZ + kb + q * 8);
            cpasync16(a, gp);
        }
    };

    float acc[4][4][4];
#pragma unroll
    for (int mi = 0; mi < 4; ++mi)
#pragma unroll
        for (int ni = 0; ni < 4; ++ni)
#pragma unroll
            for (int j = 0; j < 4; ++j) acc[mi][ni][j] = 0.f;

    fill(0, 0); CP_COMMIT();
    fill(1, 1); CP_COMMIT();
    fill(2, 2); CP_COMMIT();

    const uint32_t offA = sw32((uint32_t)((wm * 64 + (lane & 15)) * 32 + (lane >> 4) * 16));
    const uint32_t offB = sw32((uint32_t)((wn * 32 + ((lane >> 4) << 3) + (lane & 7)) * 32 +
                                          ((lane >> 3) & 1) * 16));

    for (int it = 0; it < NITER; ++it) {
        CP_WAIT(2);
        __syncthreads();
        if (it + 3 < NITER) { fill(it + 3, (it + 3) % NSTAGE); CP_COMMIT(); }

        const uint32_t st = sbase + (uint32_t)(it % NSTAGE) * STAGE_BYTES;
#pragma unroll
        for (int ch = 0; ch < 2; ++ch) {
            const uint32_t aA = st + ch * 4096 + offA;
            const uint32_t bW = st + 8192 + ch * 4096 + offB;
            uint32_t av[4][4], bw[4][2];
#pragma unroll
            for (int mi = 0; mi < 4; ++mi)
                ldsm4(av[mi], aA + (uint32_t)(mi * 16 * 32));
#pragma unroll
            for (int np = 0; np < 2; ++np) {
                uint32_t r4[4];
                ldsm4(r4, bW + (uint32_t)(np * 16 * 32));
                bw[2 * np][0] = r4[0]; bw[2 * np][1] = r4[1];
                bw[2 * np + 1][0] = r4[2]; bw[2 * np + 1][1] = r4[3];
            }
#pragma unroll
            for (int mi = 0; mi < 4; ++mi)
#pragma unroll
                for (int ni = 0; ni < 4; ++ni)
                    mma16816(acc[mi][ni], av[mi], bw[ni]);
        }
        __syncthreads();
    }

    const int gq = lane >> 2, tg = lane & 3;

    if (bx < NBLK_K) {
        const int n0 = bx * TILE_N;
        float* w12s = (float*)smem;
        float* bks  = (float*)(smem) + 128;
        float* sred = (float*)(smem) + 256;
        if (tid < 128) {
            w12s[tid] = n1w[n0 + tid] * n2w[n0 + tid];
            bks[tid]  = bk[n0 + tid];
        }
        __syncthreads();

        float pssk[8], pcr[8], pssq[8];
#pragma unroll
        for (int i = 0; i < 8; ++i) { pssk[i] = 0.f; pcr[i] = 0.f; pssq[i] = 0.f; }

#pragma unroll
        for (int mi = 0; mi < 4; ++mi) {
#pragma unroll
            for (int half = 0; half < 2; ++half) {
                int row = m0 + wm * 64 + mi * 16 + gq + half * 8;
                const float* hrow = hid + (size_t)row * CD + n0;
                int s8 = mi * 2 + half;
#pragma unroll
                for (int ni = 0; ni < 4; ++ni) {
                    int cl = wn * 32 + ni * 8 + tg * 2;
                    float2 h = *(const float2*)&hrow[cl];
                    float k0 = acc[mi][ni][half * 2 + 0] + bks[cl];
                    float k1 = acc[mi][ni][half * 2 + 1] + bks[cl + 1];
                    pssk[s8] += k0 * k0 + k1 * k1;
                    pcr[s8]  += k0 * h.x * w12s[cl] + k1 * h.y * w12s[cl + 1];
                    pssq[s8] += h.x * h.x + h.y * h.y;
                }
            }
        }
#pragma unroll
        for (int i = 0; i < 8; ++i) {
            pssk[i] += __shfl_xor_sync(0xffffffffu, pssk[i], 1);
            pssk[i] += __shfl_xor_sync(0xffffffffu, pssk[i], 2);
            pcr[i]  += __shfl_xor_sync(0xffffffffu, pcr[i], 1);
            pcr[i]  += __shfl_xor_sync(0xffffffffu, pcr[i], 2);
            pssq[i] += __shfl_xor_sync(0xffffffffu, pssq[i], 1);
            pssq[i] += __shfl_xor_sync(0xffffffffu, pssq[i], 2);
        }
        if (tg == 0) {
#pragma unroll
            for (int mi = 0; mi < 4; ++mi)
#pragma unroll
                for (int half = 0; half < 2; ++half) {
                    int rl = wm * 64 + mi * 16 + gq + half * 8;
                    int s8 = mi * 2 + half;
                    sred[0 * 512 + rl * 4 + wn] = pssk[s8];
                    sred[1 * 512 + rl * 4 + wn] = pcr[s8];
                    sred[2 * 512 + rl * 4 + wn] = pssq[s8];
                }
        }
        __syncthreads();
        if (tid < 128) {
#pragma unroll
            for (int m = 0; m < 3; ++m) {
                float s = sred[m * 512 + tid * 4 + 0] + sred[m * 512 + tid * 4 + 1] +
                          sred[m * 512 + tid * 4 + 2] + sred[m * 512 + tid * 4 + 3];
                g_partK[((size_t)m * NBLK_K + bx) * ROWS + m0 + tid] = s;
            }
        }
    } else {
        const int c0 = (bx - NBLK_K) * TILE_N;
        float* bvs  = (float*)smem;
        float* sred = (float*)(smem) + 128;
        if (tid < 128) bvs[tid] = bv[c0 + tid];
        __syncthreads();

        float psv[8];
#pragma unroll
        for (int i = 0; i < 8; ++i) psv[i] = 0.f;

#pragma unroll
        for (int mi = 0; mi < 4; ++mi) {
#pragma unroll
            for (int half = 0; half < 2; ++half) {
                int row = m0 + wm * 64 + mi * 16 + gq + half * 8;
                int s8 = mi * 2 + half;
                float* vrow = g_vpb + (size_t)row * D_SZ + c0;
#pragma unroll
                for (int ni = 0; ni < 4; ++ni) {
                    int cl = wn * 32 + ni * 8 + tg * 2;
                    float v0 = acc[mi][ni][half * 2 + 0] + bvs[cl];
                    float v1 = acc[mi][ni][half * 2 + 1] + bvs[cl + 1];
                    psv[s8] += v0 * v0 + v1 * v1;
                    float2 o; o.x = v0; o.y = v1;
                    *(float2*)&vrow[cl] = o;
                }
            }
        }
#pragma unroll
        for (int i = 0; i < 8; ++i) {
            psv[i] += __shfl_xor_sync(0xffffffffu, psv[i], 1);
            psv[i] += __shfl_xor_sync(0xffffffffu, psv[i], 2);
        }
        if (tg == 0) {
#pragma unroll
            for (int mi = 0; mi < 4; ++mi)
#pragma unroll
                for (int half = 0; half < 2; ++half) {
                    int rl = wm * 64 + mi * 16 + gq + half * 8;
                    sred[rl * 4 + wn] = psv[mi * 2 + half];
                }
        }
        __syncthreads();
        if (tid < 128) {
            float s = sred[tid * 4 + 0] + sred[tid * 4 + 1] +
                      sred[tid * 4 + 2] + sred[tid * 4 + 3];
            g_partV[(size_t)(bx - NBLK_K) * ROWS + m0 + tid] = s;
        }
    }
}

// ---------------------------------------------------------------------------
// 3) rowstats
// ---------------------------------------------------------------------------
__global__ void __launch_bounds__(256) rowstats()
{
    int r = blockIdx.x * 256 + threadIdx.x;
    float ssk[2] = {0.f, 0.f}, cr[2] = {0.f, 0.f}, ssq[2] = {0.f, 0.f};
#pragma unroll
    for (int bx = 0; bx < NBLK_K; ++bx) {
        int gg = bx >> 4;
        ssk[gg] += g_partK[((size_t)0 * NBLK_K + bx) * ROWS + r];
        cr[gg]  += g_partK[((size_t)1 * NBLK_K + bx) * ROWS + r];
        ssq[gg] += g_partK[((size_t)2 * NBLK_K + bx) * ROWS + r];
    }
    float sv = 0.f;
#pragma unroll
    for (int bx = 0; bx < NBLK_V; ++bx)
        sv += g_partV[(size_t)bx * ROWS + r];

    const float invD = 1.0f / 2048.0f;
    const float invSqrtD = 0.022097086912079610f;
    float4 rs;
    float gate[2], q[2];
#pragma unroll
    for (int gg = 0; gg < 2; ++gg) {
        float rsk = rsqrtf(ssk[gg] * invD + EPS_DEF);
        float rsq = rsqrtf(ssq[gg] * invD + EPS_DEF);
        float gt  = rsk * rsq * cr[gg] * invSqrtD;
        float sg  = (gt > 0.f) ? 1.f : ((gt < 0.f) ? -1.f : 0.f);
        float sq  = sqrtf(fmaxf(fabsf(gt), 1e-6f)) * sg;
        gate[gg] = __fdividef(1.f, 1.f + __expf(-sq));
        float inv = rsqrtf(gate[gg] * gate[gg] * sv * invD + EPS_SC);
        q[gg] = gate[gg] * inv;
    }
    rs.x = gate[0]; rs.y = gate[1]; rs.z = q[0]; rs.w = q[1];
    g_rs[r] = rs;
}

// ---------------------------------------------------------------------------
// 4) conv_out: 12 rows per thread, rolling xn window (dilation-3 causal)
// ---------------------------------------------------------------------------
__global__ void __launch_bounds__(256) conv_out(
    const float* __restrict__ cw, const float* __restrict__ scw,
    float* __restrict__ out)
{
    int t = blockIdx.x * blockDim.x + threadIdx.x;
    int c4 = t & 1023;            // CD/4 groups
    int chunk = t >> 10;          // 0 .. 4*171-1
    if (chunk >= B_SZ * NCHUNK) return;
    int b = chunk / NCHUNK;
    int l0 = (chunk - b * NCHUNK) * LCH;
    int cnt = (L_SZ - l0 < LCH) ? (L_SZ - l0) : LCH;

    int c = c4 << 2;
    int gg = c >> 11;
    int d  = c & (D_SZ - 1);
    int rbase = b * L_SZ;

    float4 w0 = *(const float4*)(cw + (size_t)c * 4);
    float4 w1 = *(const float4*)(cw + (size_t)(c + 1) * 4);
    float4 w2 = *(const float4*)(cw + (size_t)(c + 2) * 4);
    float4 w3 = *(const float4*)(cw + (size_t)(c + 3) * 4);
    float4 sc = *(const float4*)(scw + c);

    float4 win[LCH];
#pragma unroll
    for (int j = 1; j <= 9; ++j)
        win[LCH - j] = make_float4(0.f, 0.f, 0.f, 0.f);
    int npre = (l0 < 9) ? l0 : 9;
#pragma unroll
    for (int j = 1; j <= 9; ++j) {
        if (j <= npre) {
            int r = rbase + l0 - j;
            float4 vv = *(const float4*)(g_vpb + (size_t)r * D_SZ + d);
            float4 rp = g_rs[r];
            float q = gg ? rp.w : rp.z;
            float4 x;
            x.x = vv.x * q * sc.x; x.y = vv.y * q * sc.y;
            x.z = vv.z * q * sc.z; x.w = vv.w * q * sc.w;
            win[LCH - j] = x;
        }
    }

#pragma unroll
    for (int i = 0; i < LCH; ++i) {
        if (i >= cnt) break;
        int l = l0 + i;
        int r = rbase + l;
        float4 vo = *(const float4*)(g_vpb + (size_t)r * D_SZ + d);
        float4 rp = g_rs[r];
        float gate = gg ? rp.y : rp.x;
        float q    = gg ? rp.w : rp.z;
        float4 x;
        x.x = vo.x * q * sc.x; x.y = vo.y * q * sc.y;
        x.z = vo.z * q * sc.z; x.w = vo.w * q * sc.w;
        win[i] = x;

        float a0 = w0.w * x.x, a1 = w1.w * x.y, a2 = w2.w * x.z, a3 = w3.w * x.w;
        {
            float4 t3 = win[(i + 9) % LCH];   // l-3
            a0 += w0.z * t3.x; a1 += w1.z * t3.y;
            a2 += w2.z * t3.z; a3 += w3.z * t3.w;
            float4 t6 = win[(i + 6) % LCH];   // l-6
            a0 += w0.y * t6.x; a1 += w1.y * t6.y;
            a2 += w2.y * t6.z; a3 += w3.y * t6.w;
            float4 t9 = win[(i + 3) % LCH];   // l-9
            a0 += w0.x * t9.x; a1 += w1.x * t9.y;
            a2 += w2.x * t9.z; a3 += w3.x * t9.w;
        }
        float4 o;
        o.x = gate * vo.x + silu_fast(a0);
        o.y = gate * vo.y + silu_fast(a1);
        o.z = gate * vo.z + silu_fast(a2);
        o.w = gate * vo.w + silu_fast(a3);
        *(float4*)&out[(size_t)r * CD + c] = o;

        if (l >= L_SZ - PAD) {
            int j = l - (L_SZ - PAD);
            size_t cbase = OUT_ELEMS + (size_t)b * CD * PAD;
            out[cbase + (size_t)(c + 0) * PAD + j] = x.x;
            out[cbase + (size_t)(c + 1) * PAD + j] = x.y;
            out[cbase + (size_t)(c + 2) * PAD + j] = x.z;
            out[cbase + (size_t)(c + 3) * PAD + j] = x.w;
        }
    }
}

// ---------------------------------------------------------------------------
// launch
// ---------------------------------------------------------------------------
extern "C" void kernel_launch(void* const* d_in, const int* in_sizes, int n_in,
                              void* d_out, int out_size)
{
    const float* hid   = (const float*)d_in[0];
    const int*   ids   = (const int*)  d_in[1];
    const float* table = (const float*)d_in[2];
    const float* Wk    = (const float*)d_in[3];
    const float* bk    = (const float*)d_in[4];
    const float* Wv    = (const float*)d_in[5];
    const float* bv    = (const float*)d_in[6];
    const float* n1    = (const float*)d_in[7];
    const float* n2    = (const float*)d_in[8];
    const float* cw    = (const float*)d_in[9];
    const float* scw   = (const float*)d_in[10];
    float* out = (float*)d_out;

    cudaFuncSetAttribute(gemm_fused, cudaFuncAttributeMaxDynamicSharedMemorySize,
                         SMEM_TOTAL);

    prep<<<ROWS + CONVW_BLOCKS, 256>>>(ids, table, Wk, Wv);
    gemm_fused<<<dim3(NTOT / TILE_N, ROWS / TILE_M), 256, SMEM_TOTAL>>>(
        bk, bv, hid, n1, n2);
    rowstats<<<ROWS / 256, 256>>>();
    int conv_threads = 1024 * B_SZ * NCHUNK;
    conv_out<<<(conv_threads + 255) / 256, 256>>>(cw, scw, out);
}

// round 12
// speedup vs baseline: 5.7123x; 1.0301x over previous
#include <cuda_runtime.h>
#include <cuda_fp16.h>
#include <math.h>
#include <stdint.h>

// ---------------------------------------------------------------------------
// Problem constants
// ---------------------------------------------------------------------------
#define B_SZ 4
#define L_SZ 2048
#define G_SZ 2
#define D_SZ 2048
#define H_SZ 16
#define DE_SZ 64
#define E_SZ 1024
#define N_SZ 32768
#define ROWS (B_SZ * L_SZ)  // 8192
#define CD (G_SZ * D_SZ)    // 4096
#define NTOT 6144
#define PAD 9
#define OUT_ELEMS ((size_t)ROWS * CD)
#define EPS_DEF 1.1920928955078125e-7f
#define EPS_SC 1e-5f

#define TILE_M 128
#define TILE_N 128
#define BK 32
#define NITER (E_SZ / BK)      // 32
#define STAGE_BYTES 16384      // A 8K | W 8K
#define NSTAGE 4
#define SMEM_TOTAL (NSTAGE * STAGE_BYTES) // 65536
#define NBLK_K 32
#define NBLK_V 16
#define CONVW_BLOCKS ((NTOT * E_SZ / 4) / 256) // 6144

#define LCH 12                 // rows per conv thread
#define NCHUNK 171             // ceil(2048/12)

// ---------------------------------------------------------------------------
// Scratch
// ---------------------------------------------------------------------------
__device__ __half g_ea[(size_t)ROWS * E_SZ];
__device__ __half g_wh[(size_t)NTOT * E_SZ];
__device__ float  g_vpb[(size_t)ROWS * D_SZ];
__device__ float  g_partK[3 * NBLK_K * (size_t)ROWS]; // [m][blk][row]
__device__ float  g_partV[NBLK_V * (size_t)ROWS];     // [blk][row]
__device__ float4 g_rs[ROWS];                         // {gate0, gate1, q0, q1}

// ---------------------------------------------------------------------------
// PTX helpers
// ---------------------------------------------------------------------------
__device__ __forceinline__ uint32_t smem_to_u32(const void* p) {
    uint32_t a;
    asm("{ .reg .u64 t; cvta.to.shared.u64 t, %1; cvt.u32.u64 %0, t; }"
        : "=r"(a) : "l"(p));
    return a;
}
__device__ __forceinline__ void cpasync16(uint32_t s, const void* g) {
    asm volatile("cp.async.cg.shared.global [%0], [%1], 16;" :: "r"(s), "l"(g));
}
#define CP_COMMIT() asm volatile("cp.async.commit_group;" ::: "memory")
#define CP_WAIT(n)  asm volatile("cp.async.wait_group %0;" :: "n"(n) : "memory")

__device__ __forceinline__ void ldsm4(uint32_t* r, uint32_t a) {
    asm volatile("ldmatrix.sync.aligned.m8n8.x4.shared.b16 {%0,%1,%2,%3}, [%4];"
        : "=r"(r[0]), "=r"(r[1]), "=r"(r[2]), "=r"(r[3]) : "r"(a));
}
__device__ __forceinline__ void mma16816(float* c, const uint32_t* a, const uint32_t* b) {
    asm volatile(
        "mma.sync.aligned.m16n8k16.row.col.f32.f16.f16.f32 "
        "{%0,%1,%2,%3}, {%4,%5,%6,%7}, {%8,%9}, {%0,%1,%2,%3};"
        : "+f"(c[0]), "+f"(c[1]), "+f"(c[2]), "+f"(c[3])
        : "r"(a[0]), "r"(a[1]), "r"(a[2]), "r"(a[3]), "r"(b[0]), "r"(b[1]));
}
__device__ __forceinline__ uint32_t sw32(uint32_t o) { return o ^ ((o >> 3) & 0x10); }

__device__ __forceinline__ float silu_fast(float a) {
    return __fdividef(a, 1.f + __expf(-a));
}

// ---------------------------------------------------------------------------
// 1) prep: gather emb->fp16 + convert W->fp16
// ---------------------------------------------------------------------------
__global__ void __launch_bounds__(256) prep(
    const int* __restrict__ ids, const float* __restrict__ table,
    const float* __restrict__ Wk, const float* __restrict__ Wv)
{
    int blk = blockIdx.x;
    int t = threadIdx.x;
    if (blk < ROWS) {
        int r = blk;
        const int* idr = ids + r * H_SZ;
        int e  = t * 4;
        int h  = e >> 6;
        int de = e & 63;
        int id = idr[h];
        float4 v = *(const float4*)&table[((size_t)(h * N_SZ + id)) * DE_SZ + de];
        __half2 p0, p1;
        p0.x = __float2half_rn(v.x); p0.y = __float2half_rn(v.y);
        p1.x = __float2half_rn(v.z); p1.y = __float2half_rn(v.w);
        *(__half2*)&g_ea[(size_t)r * E_SZ + e]     = p0;
        *(__half2*)&g_ea[(size_t)r * E_SZ + e + 2] = p1;
    } else {
        size_t idx = ((size_t)(blk - ROWS) * 256 + t) * 4;
        size_t n = idx >> 10;
        const float* src = (n < 4096) ? (Wk + idx)
                                      : (Wv + (idx - (size_t)4096 * E_SZ));
        float4 v = *(const float4*)src;
        __half2 h0, h1;
        h0.x = __float2half_rn(v.x); h0.y = __float2half_rn(v.y);
        h1.x = __float2half_rn(v.z); h1.y = __float2half_rn(v.w);
        *(__half2*)&g_wh[idx]     = h0;
        *(__half2*)&g_wh[idx + 2] = h1;
    }
}

// ---------------------------------------------------------------------------
// 2) Merged fp16 GEMM, 128x128 tiles, 2 CTAs/SM
// ---------------------------------------------------------------------------
__global__ void __launch_bounds__(256, 2) gemm_fused(
    const float* __restrict__ bk, const float* __restrict__ bv,
    const float* __restrict__ hid,
    const float* __restrict__ n1w, const float* __restrict__ n2w)
{
    extern __shared__ __align__(1024) char smem[];
    const uint32_t sbase = smem_to_u32(smem);
    const int tid = threadIdx.x, wid = tid >> 5, lane = tid & 31;
    const int bx = blockIdx.x;
    const int m0 = blockIdx.y * TILE_M;
    const int n0w = bx * TILE_N;
    const int wm = wid & 1, wn = wid >> 1;

    auto fill = [&](int kt, int s) {
        const uint32_t st = sbase + (uint32_t)s * STAGE_BYTES;
        const int kb = kt * BK;
#pragma unroll
        for (int i = 0; i < 4; ++i) {
            int u = tid + i * 256;
            int isW = (u >= 512);
            int v = u & 511;
            int r = v >> 2, q = v & 3;
            uint32_t a = st + isW * 8192 + (q >> 1) * 4096 +
                         sw32((uint32_t)(r * 32 + (q & 1) * 16));
            const __half* gp = isW ? (g_wh + (size_t)(n0w + r) * E_SZ + kb + q * 8)
                                   : (g_ea + (size_t)(m0 + r) * E_SZ + kb + q * 8);
            cpasync16(a, gp);
        }
    };

    float acc[4][4][4];
#pragma unroll
    for (int mi = 0; mi < 4; ++mi)
#pragma unroll
        for (int ni = 0; ni < 4; ++ni)
#pragma unroll
            for (int j = 0; j < 4; ++j) acc[mi][ni][j] = 0.f;

    fill(0, 0); CP_COMMIT();
    fill(1, 1); CP_COMMIT();
    fill(2, 2); CP_COMMIT();

    const uint32_t offA = sw32((uint32_t)((wm * 64 + (lane & 15)) * 32 + (lane >> 4) * 16));
    const uint32_t offB = sw32((uint32_t)((wn * 32 + ((lane >> 4) << 3) + (lane & 7)) * 32 +
                                          ((lane >> 3) & 1) * 16));

    for (int it = 0; it < NITER; ++it) {
        CP_WAIT(2);
        __syncthreads();
        if (it + 3 < NITER) { fill(it + 3, (it + 3) % NSTAGE); CP_COMMIT(); }

        const uint32_t st = sbase + (uint32_t)(it % NSTAGE) * STAGE_BYTES;
#pragma unroll
        for (int ch = 0; ch < 2; ++ch) {
            const uint32_t aA = st + ch * 4096 + offA;
            const uint32_t bW = st + 8192 + ch * 4096 + offB;
            uint32_t av[4][4], bw[4][2];
#pragma unroll
            for (int mi = 0; mi < 4; ++mi)
                ldsm4(av[mi], aA + (uint32_t)(mi * 16 * 32));
#pragma unroll
            for (int np = 0; np < 2; ++np) {
                uint32_t r4[4];
                ldsm4(r4, bW + (uint32_t)(np * 16 * 32));
                bw[2 * np][0] = r4[0]; bw[2 * np][1] = r4[1];
                bw[2 * np + 1][0] = r4[2]; bw[2 * np + 1][1] = r4[3];
            }
#pragma unroll
            for (int mi = 0; mi < 4; ++mi)
#pragma unroll
                for (int ni = 0; ni < 4; ++ni)
                    mma16816(acc[mi][ni], av[mi], bw[ni]);
        }
        __syncthreads();
    }

    const int gq = lane >> 2, tg = lane & 3;

    if (bx < NBLK_K) {
        const int n0 = bx * TILE_N;
        float* w12s = (float*)smem;
        float* bks  = (float*)(smem) + 128;
        float* sred = (float*)(smem) + 256;
        if (tid < 128) {
            w12s[tid] = n1w[n0 + tid] * n2w[n0 + tid];
            bks[tid]  = bk[n0 + tid];
        }
        __syncthreads();

        float pssk[8], pcr[8], pssq[8];
#pragma unroll
        for (int i = 0; i < 8; ++i) { pssk[i] = 0.f; pcr[i] = 0.f; pssq[i] = 0.f; }

#pragma unroll
        for (int mi = 0; mi < 4; ++mi) {
#pragma unroll
            for (int half = 0; half < 2; ++half) {
                int row = m0 + wm * 64 + mi * 16 + gq + half * 8;
                const float* hrow = hid + (size_t)row * CD + n0;
                int s8 = mi * 2 + half;
#pragma unroll
                for (int ni = 0; ni < 4; ++ni) {
                    int cl = wn * 32 + ni * 8 + tg * 2;
                    float2 h = *(const float2*)&hrow[cl];
                    float k0 = acc[mi][ni][half * 2 + 0] + bks[cl];
                    float k1 = acc[mi][ni][half * 2 + 1] + bks[cl + 1];
                    pssk[s8] += k0 * k0 + k1 * k1;
                    pcr[s8]  += k0 * h.x * w12s[cl] + k1 * h.y * w12s[cl + 1];
                    pssq[s8] += h.x * h.x + h.y * h.y;
                }
            }
        }
#pragma unroll
        for (int i = 0; i < 8; ++i) {
            pssk[i] += __shfl_xor_sync(0xffffffffu, pssk[i], 1);
            pssk[i] += __shfl_xor_sync(0xffffffffu, pssk[i], 2);
            pcr[i]  += __shfl_xor_sync(0xffffffffu, pcr[i], 1);
            pcr[i]  += __shfl_xor_sync(0xffffffffu, pcr[i], 2);
            pssq[i] += __shfl_xor_sync(0xffffffffu, pssq[i], 1);
            pssq[i] += __shfl_xor_sync(0xffffffffu, pssq[i], 2);
        }
        if (tg == 0) {
#pragma unroll
            for (int mi = 0; mi < 4; ++mi)
#pragma unroll
                for (int half = 0; half < 2; ++half) {
                    int rl = wm * 64 + mi * 16 + gq + half * 8;
                    int s8 = mi * 2 + half;
                    sred[0 * 512 + rl * 4 + wn] = pssk[s8];
                    sred[1 * 512 + rl * 4 + wn] = pcr[s8];
                    sred[2 * 512 + rl * 4 + wn] = pssq[s8];
                }
        }
        __syncthreads();
        if (tid < 128) {
#pragma unroll
            for (int m = 0; m < 3; ++m) {
                float s = sred[m * 512 + tid * 4 + 0] + sred[m * 512 + tid * 4 + 1] +
                          sred[m * 512 + tid * 4 + 2] + sred[m * 512 + tid * 4 + 3];
                g_partK[((size_t)m * NBLK_K + bx) * ROWS + m0 + tid] = s;
            }
        }
    } else {
        const int c0 = (bx - NBLK_K) * TILE_N;
        float* bvs  = (float*)smem;
        float* sred = (float*)(smem) + 128;
        if (tid < 128) bvs[tid] = bv[c0 + tid];
        __syncthreads();

        float psv[8];
#pragma unroll
        for (int i = 0; i < 8; ++i) psv[i] = 0.f;

#pragma unroll
        for (int mi = 0; mi < 4; ++mi) {
#pragma unroll
            for (int half = 0; half < 2; ++half) {
                int row = m0 + wm * 64 + mi * 16 + gq + half * 8;
                int s8 = mi * 2 + half;
                float* vrow = g_vpb + (size_t)row * D_SZ + c0;
#pragma unroll
                for (int ni = 0; ni < 4; ++ni) {
                    int cl = wn * 32 + ni * 8 + tg * 2;
                    float v0 = acc[mi][ni][half * 2 + 0] + bvs[cl];
                    float v1 = acc[mi][ni][half * 2 + 1] + bvs[cl + 1];
                    psv[s8] += v0 * v0 + v1 * v1;
                    float2 o; o.x = v0; o.y = v1;
                    *(float2*)&vrow[cl] = o;
                }
            }
        }
#pragma unroll
        for (int i = 0; i < 8; ++i) {
            psv[i] += __shfl_xor_sync(0xffffffffu, psv[i], 1);
            psv[i] += __shfl_xor_sync(0xffffffffu, psv[i], 2);
        }
        if (tg == 0) {
#pragma unroll
            for (int mi = 0; mi < 4; ++mi)
#pragma unroll
                for (int half = 0; half < 2; ++half) {
                    int rl = wm * 64 + mi * 16 + gq + half * 8;
                    sred[rl * 4 + wn] = psv[mi * 2 + half];
                }
        }
        __syncthreads();
        if (tid < 128) {
            float s = sred[tid * 4 + 0] + sred[tid * 4 + 1] +
                      sred[tid * 4 + 2] + sred[tid * 4 + 3];
            g_partV[(size_t)(bx - NBLK_K) * ROWS + m0 + tid] = s;
        }
    }
}

// ---------------------------------------------------------------------------
// 3) rowstats
// ---------------------------------------------------------------------------
__global__ void __launch_bounds__(256) rowstats()
{
    int r = blockIdx.x * 256 + threadIdx.x;
    float ssk[2] = {0.f, 0.f}, cr[2] = {0.f, 0.f}, ssq[2] = {0.f, 0.f};
#pragma unroll
    for (int bx = 0; bx < NBLK_K; ++bx) {
        int gg = bx >> 4;
        ssk[gg] += g_partK[((size_t)0 * NBLK_K + bx) * ROWS + r];
        cr[gg]  += g_partK[((size_t)1 * NBLK_K + bx) * ROWS + r];
        ssq[gg] += g_partK[((size_t)2 * NBLK_K + bx) * ROWS + r];
    }
    float sv = 0.f;
#pragma unroll
    for (int bx = 0; bx < NBLK_V; ++bx)
        sv += g_partV[(size_t)bx * ROWS + r];

    const float invD = 1.0f / 2048.0f;
    const float invSqrtD = 0.022097086912079610f;
    float4 rs;
    float gate[2], q[2];
#pragma unroll
    for (int gg = 0; gg < 2; ++gg) {
        float rsk = rsqrtf(ssk[gg] * invD + EPS_DEF);
        float rsq = rsqrtf(ssq[gg] * invD + EPS_DEF);
        float gt  = rsk * rsq * cr[gg] * invSqrtD;
        float sg  = (gt > 0.f) ? 1.f : ((gt < 0.f) ? -1.f : 0.f);
        float sq  = sqrtf(fmaxf(fabsf(gt), 1e-6f)) * sg;
        gate[gg] = __fdividef(1.f, 1.f + __expf(-sq));
        float inv = rsqrtf(gate[gg] * gate[gg] * sv * invD + EPS_SC);
        q[gg] = gate[gg] * inv;
    }
    rs.x = gate[0]; rs.y = gate[1]; rs.z = q[0]; rs.w = q[1];
    g_rs[r] = rs;
}

// ---------------------------------------------------------------------------
// 4) conv_out: 12 rows per thread, 2 channels, rolling xn window
//    thread -> (c2 group, batch, 12-row chunk). Warp = 32 consecutive c2.
// ---------------------------------------------------------------------------
__global__ void __launch_bounds__(256) conv_out(
    const float* __restrict__ cw, const float* __restrict__ scw,
    float* __restrict__ out)
{
    int t = blockIdx.x * blockDim.x + threadIdx.x;
    int c2 = t & 2047;            // CD/2 groups
    int chunk = t >> 11;          // 0 .. 4*171-1
    if (chunk >= B_SZ * NCHUNK) return;
    int b = chunk / NCHUNK;
    int l0 = (chunk - b * NCHUNK) * LCH;
    int cnt = (L_SZ - l0 < LCH) ? (L_SZ - l0) : LCH;

    int c = c2 << 1;
    int gg = c >> 11;
    int d  = c & (D_SZ - 1);
    int rbase = b * L_SZ;

    float4 w0 = *(const float4*)(cw + (size_t)c * 4);
    float4 w1 = *(const float4*)(cw + (size_t)(c + 1) * 4);
    float2 sc = *(const float2*)(scw + c);

    float2 win[LCH];
#pragma unroll
    for (int j = 1; j <= 9; ++j)
        win[LCH - j] = make_float2(0.f, 0.f);
    int npre = (l0 < 9) ? l0 : 9;
#pragma unroll
    for (int j = 1; j <= 9; ++j) {
        if (j <= npre) {
            int r = rbase + l0 - j;
            float2 vv = *(const float2*)(g_vpb + (size_t)r * D_SZ + d);
            float4 rp = g_rs[r];
            float q = gg ? rp.w : rp.z;
            float2 x;
            x.x = vv.x * q * sc.x; x.y = vv.y * q * sc.y;
            win[LCH - j] = x;
        }
    }

#pragma unroll
    for (int i = 0; i < LCH; ++i) {
        if (i >= cnt) break;
        int l = l0 + i;
        int r = rbase + l;
        float2 vo = *(const float2*)(g_vpb + (size_t)r * D_SZ + d);
        float4 rp = g_rs[r];
        float gate = gg ? rp.y : rp.x;
        float q    = gg ? rp.w : rp.z;
        float2 x;
        x.x = vo.x * q * sc.x; x.y = vo.y * q * sc.y;
        win[i] = x;

        float a0 = w0.w * x.x, a1 = w1.w * x.y;
        {
            float2 t3 = win[(i + 9) % LCH];   // l-3
            a0 += w0.z * t3.x; a1 += w1.z * t3.y;
            float2 t6 = win[(i + 6) % LCH];   // l-6
            a0 += w0.y * t6.x; a1 += w1.y * t6.y;
            float2 t9 = win[(i + 3) % LCH];   // l-9
            a0 += w0.x * t9.x; a1 += w1.x * t9.y;
        }
        float2 o;
        o.x = gate * vo.x + silu_fast(a0);
        o.y = gate * vo.y + silu_fast(a1);
        *(float2*)&out[(size_t)r * CD + c] = o;

        if (l >= L_SZ - PAD) {
            int j = l - (L_SZ - PAD);
            size_t cbase = OUT_ELEMS + (size_t)b * CD * PAD;
            out[cbase + (size_t)(c + 0) * PAD + j] = x.x;
            out[cbase + (size_t)(c + 1) * PAD + j] = x.y;
        }
    }
}

// ---------------------------------------------------------------------------
// launch
// ---------------------------------------------------------------------------
extern "C" void kernel_launch(void* const* d_in, const int* in_sizes, int n_in,
                              void* d_out, int out_size)
{
    const float* hid   = (const float*)d_in[0];
    const int*   ids   = (const int*)  d_in[1];
    const float* table = (const float*)d_in[2];
    const float* Wk    = (const float*)d_in[3];
    const float* bk    = (const float*)d_in[4];
    const float* Wv    = (const float*)d_in[5];
    const float* bv    = (const float*)d_in[6];
    const float* n1    = (const float*)d_in[7];
    const float* n2    = (const float*)d_in[8];
    const float* cw    = (const float*)d_in[9];
    const float* scw   = (const float*)d_in[10];
    float* out = (float*)d_out;

    cudaFuncSetAttribute(gemm_fused, cudaFuncAttributeMaxDynamicSharedMemorySize,
                         SMEM_TOTAL);

    prep<<<ROWS + CONVW_BLOCKS, 256>>>(ids, table, Wk, Wv);
    gemm_fused<<<dim3(NTOT / TILE_N, ROWS / TILE_M), 256, SMEM_TOTAL>>>(
        bk, bv, hid, n1, n2);
    rowstats<<<ROWS / 256, 256>>>();
    int conv_threads = 2048 * B_SZ * NCHUNK;
    conv_out<<<(conv_threads + 255) / 256, 256>>>(cw, scw, out);
}